// round 2
// baseline (speedup 1.0000x reference)
#include <cuda_runtime.h>
#include <cuda_bf16.h>

// Problem constants
//   x  : [512, 128, 768]  fp32
//   Wq/Wk/Wv: [768, 768], Wo: [768, 768], bo: [768]
//   out: [512, 128, 768]  fp32
// H = 12 heads, hd = 64.

#define NB   512
#define NT   128
#define ND   768
#define NH   12
#define NHD  64
#define BT   (NB * NT)          // 65536

// Scratch: Q,K,V in [b,h,t,hd] layout; ctx in [b,t,d] layout.
__device__ float g_q[NB * NH * NT * NHD];
__device__ float g_k[NB * NH * NT * NHD];
__device__ float g_v[NB * NH * NT * NHD];
__device__ float g_ctx[NB * NT * ND];

// ---------------------------------------------------------------------------
// SGEMM: C[M=65536, N=768] = A[65536,768] * W[768,768] (+bias)
// 128x128 block tile, BK=8, 256 threads, 8x8 per-thread microtile.
// PERMUTE: write C into [b,h,t,hd] layout (for Q/K/V).
// BIAS:    add bias[col] (for output projection).
// ---------------------------------------------------------------------------
template <bool PERMUTE, bool BIAS>
__global__ __launch_bounds__(256) void sgemm128(
    const float* __restrict__ A, const float* __restrict__ W,
    float* __restrict__ C, const float* __restrict__ bias)
{
    __shared__ float As[8][128];   // transposed A tile: As[k][m]
    __shared__ float Bs[8][128];   // Bs[k][n]

    const int tid = threadIdx.x;
    const int bx = blockIdx.x;     // 0..5   (N/128)
    const int by = blockIdx.y;     // 0..511 (M/128)

    const int ty = tid >> 4;       // 0..15
    const int tx = tid & 15;       // 0..15

    const int arow  = (by << 7) + (tid >> 1);      // global A row
    const int akoff = (tid & 1) << 2;              // 0 or 4 within BK
    const int brow  = tid >> 5;                    // 0..7 within BK
    const int bcoff = (tid & 31) << 2;             // 0..124 within BN
    const int bcol  = (bx << 7) + bcoff;

    float acc[8][8];
#pragma unroll
    for (int i = 0; i < 8; i++)
#pragma unroll
        for (int j = 0; j < 8; j++) acc[i][j] = 0.f;

    for (int kb = 0; kb < 768; kb += 8) {
        float4 av = *(const float4*)(A + (size_t)arow * 768 + kb + akoff);
        float4 bv = *(const float4*)(W + (size_t)(kb + brow) * 768 + bcol);

        As[akoff + 0][tid >> 1] = av.x;
        As[akoff + 1][tid >> 1] = av.y;
        As[akoff + 2][tid >> 1] = av.z;
        As[akoff + 3][tid >> 1] = av.w;
        *(float4*)&Bs[brow][bcoff] = bv;
        __syncthreads();

#pragma unroll
        for (int k = 0; k < 8; k++) {
            float a[8], b[8];
            *(float4*)(a    ) = *(const float4*)&As[k][ty * 8];
            *(float4*)(a + 4) = *(const float4*)&As[k][ty * 8 + 4];
            *(float4*)(b    ) = *(const float4*)&Bs[k][tx * 8];
            *(float4*)(b + 4) = *(const float4*)&Bs[k][tx * 8 + 4];
#pragma unroll
            for (int i = 0; i < 8; i++)
#pragma unroll
                for (int j = 0; j < 8; j++)
                    acc[i][j] = fmaf(a[i], b[j], acc[i][j]);
        }
        __syncthreads();
    }

#pragma unroll
    for (int i = 0; i < 8; i++) {
        const int r = (by << 7) + ty * 8 + i;
#pragma unroll
        for (int j = 0; j < 8; j++) {
            const int c = (bx << 7) + tx * 8 + j;
            if (PERMUTE) {
                const int b = r >> 7, t = r & 127;
                const int h = c >> 6, d = c & 63;
                C[((((size_t)(b * NH + h)) << 7 | t) << 6) | d] = acc[i][j];
            } else if (BIAS) {
                C[(size_t)r * 768 + c] = acc[i][j] + bias[c];
            } else {
                C[(size_t)r * 768 + c] = acc[i][j];
            }
        }
    }
}

// ---------------------------------------------------------------------------
// Fused attention: one CTA per (b,h). T=128, hd=64.
// Smem layout:
//   Qt[64][132]  (transposed: Qt[d][i])
//   Kt[64][132]  (transposed: Kt[d][j])
//   Vs[128][68]  (row-major:  Vs[j][d])
//   St[128][132] (transposed scores/probs: St[j][i] = P[i][j])
// ---------------------------------------------------------------------------
#define QT_STRIDE 132
#define V_STRIDE  68
#define ST_STRIDE 132
#define ATTN_SMEM ((64 * QT_STRIDE * 2 + 128 * V_STRIDE + 128 * ST_STRIDE) * 4)

__global__ __launch_bounds__(256, 1) void attn_kernel(
    const float* __restrict__ q, const float* __restrict__ k,
    const float* __restrict__ v, float* __restrict__ ctx)
{
    extern __shared__ float sm[];
    float* Qt = sm;
    float* Kt = Qt + 64 * QT_STRIDE;
    float* Vs = Kt + 64 * QT_STRIDE;
    float* St = Vs + 128 * V_STRIDE;

    const int tid = threadIdx.x;
    const int bh  = blockIdx.x;
    const int b   = bh / NH;
    const int h   = bh - b * NH;
    const size_t base = (size_t)bh * (NT * NHD);

    const float4* q4 = (const float4*)(q + base);
    const float4* k4 = (const float4*)(k + base);
    const float4* v4 = (const float4*)(v + base);

    // Load Q,K transposed; V row-major. 128*64 floats = 2048 float4 each.
    for (int idx = tid; idx < 2048; idx += 256) {
        const int row = idx >> 4;
        const int d   = (idx & 15) << 2;
        float4 aq = q4[idx];
        float4 ak = k4[idx];
        float4 av = v4[idx];
        Qt[(d + 0) * QT_STRIDE + row] = aq.x;
        Qt[(d + 1) * QT_STRIDE + row] = aq.y;
        Qt[(d + 2) * QT_STRIDE + row] = aq.z;
        Qt[(d + 3) * QT_STRIDE + row] = aq.w;
        Kt[(d + 0) * QT_STRIDE + row] = ak.x;
        Kt[(d + 1) * QT_STRIDE + row] = ak.y;
        Kt[(d + 2) * QT_STRIDE + row] = ak.z;
        Kt[(d + 3) * QT_STRIDE + row] = ak.w;
        *(float4*)&Vs[row * V_STRIDE + d] = av;
    }
    __syncthreads();

    const int ty = tid >> 4, tx = tid & 15;
    const int i0 = ty * 8, j0 = tx * 8;

    // Scores: S[i][j] = sum_d Q[i][d] * K[j][d]
    {
        float acc[8][8];
#pragma unroll
        for (int i = 0; i < 8; i++)
#pragma unroll
            for (int j = 0; j < 8; j++) acc[i][j] = 0.f;

        for (int d = 0; d < 64; d++) {
            float a[8], bb[8];
            *(float4*)(a     ) = *(const float4*)&Qt[d * QT_STRIDE + i0];
            *(float4*)(a + 4 ) = *(const float4*)&Qt[d * QT_STRIDE + i0 + 4];
            *(float4*)(bb    ) = *(const float4*)&Kt[d * QT_STRIDE + j0];
            *(float4*)(bb + 4) = *(const float4*)&Kt[d * QT_STRIDE + j0 + 4];
#pragma unroll
            for (int i = 0; i < 8; i++)
#pragma unroll
                for (int j = 0; j < 8; j++)
                    acc[i][j] = fmaf(a[i], bb[j], acc[i][j]);
        }
        // Store transposed: St[j][i]
#pragma unroll
        for (int j = 0; j < 8; j++)
#pragma unroll
            for (int i = 0; i < 8; i++)
                St[(j0 + j) * ST_STRIDE + (i0 + i)] = acc[i][j];
    }
    __syncthreads();

    // Causal softmax, one row per thread (tid < 128). Reads St column i.
    if (tid < 128) {
        const int i = tid;
        const float scale = 0.125f;  // 1/sqrt(64)
        float m = -1e30f;
        for (int j = 0; j <= i; j++) {
            float s = St[j * ST_STRIDE + i] * scale;
            m = fmaxf(m, s);
        }
        float sum = 0.f;
        for (int j = 0; j <= i; j++) {
            float e = __expf(St[j * ST_STRIDE + i] * scale - m);
            St[j * ST_STRIDE + i] = e;
            sum += e;
        }
        for (int j = i + 1; j < 128; j++) St[j * ST_STRIDE + i] = 0.f;
        const float inv = 1.f / sum;
        for (int j = 0; j <= i; j++) St[j * ST_STRIDE + i] *= inv;
    }
    __syncthreads();

    // ctx[i][d] = sum_j P[i][j] * V[j][d].  8 rows x 4 cols per thread.
    {
        const int d0 = tx << 2;
        float acc[8][4];
#pragma unroll
        for (int i = 0; i < 8; i++)
#pragma unroll
            for (int d = 0; d < 4; d++) acc[i][d] = 0.f;

        for (int j = 0; j < 128; j++) {
            float a[8], bb[4];
            *(float4*)(a    ) = *(const float4*)&St[j * ST_STRIDE + i0];
            *(float4*)(a + 4) = *(const float4*)&St[j * ST_STRIDE + i0 + 4];
            *(float4*)(bb   ) = *(const float4*)&Vs[j * V_STRIDE + d0];
#pragma unroll
            for (int i = 0; i < 8; i++)
#pragma unroll
                for (int d = 0; d < 4; d++)
                    acc[i][d] = fmaf(a[i], bb[d], acc[i][d]);
        }
        // ctx layout [B, T, D], d-column = h*64 + d0..d0+3
#pragma unroll
        for (int i = 0; i < 8; i++) {
            const size_t addr = ((size_t)(b * NT + i0 + i)) * ND + h * NHD + d0;
            float4 val = make_float4(acc[i][0], acc[i][1], acc[i][2], acc[i][3]);
            *(float4*)&ctx[addr] = val;
        }
    }
}

extern "C" void kernel_launch(void* const* d_in, const int* in_sizes, int n_in,
                              void* d_out, int out_size)
{
    const float* x  = (const float*)d_in[0];
    const float* Wq = (const float*)d_in[1];
    const float* Wk = (const float*)d_in[2];
    const float* Wv = (const float*)d_in[3];
    const float* Wo = (const float*)d_in[4];
    const float* bo = (const float*)d_in[5];
    float* out = (float*)d_out;

    void *pq, *pk, *pv, *pctx;
    cudaGetSymbolAddress(&pq,  g_q);
    cudaGetSymbolAddress(&pk,  g_k);
    cudaGetSymbolAddress(&pv,  g_v);
    cudaGetSymbolAddress(&pctx, g_ctx);

    dim3 grid(ND / 128, BT / 128);   // (6, 512)

    sgemm128<true, false><<<grid, 256>>>(x, Wq, (float*)pq, nullptr);
    sgemm128<true, false><<<grid, 256>>>(x, Wk, (float*)pk, nullptr);
    sgemm128<true, false><<<grid, 256>>>(x, Wv, (float*)pv, nullptr);

    cudaFuncSetAttribute(attn_kernel,
                         cudaFuncAttributeMaxDynamicSharedMemorySize, ATTN_SMEM);
    attn_kernel<<<NB * NH, 256, ATTN_SMEM>>>((const float*)pq, (const float*)pk,
                                             (const float*)pv, (float*)pctx);

    sgemm128<false, true><<<grid, 256>>>((const float*)pctx, Wo, out, bo);
}

// round 5
// speedup vs baseline: 3.1642x; 3.1642x over previous
#include <cuda_runtime.h>
#include <cuda_bf16.h>
#include <cstdint>

// Problem: x[512,128,768] fp32; Wq/k/v/o [768,768]; bo[768]; out[512,128,768] fp32.
#define NB   512
#define NT   128
#define ND   768
#define NH   12
#define NHD  64
#define BT   (NB * NT)          // 65536

// ---------------- scratch (__device__ globals; no allocs allowed) ----------
__device__ float g_q[NB * NH * NT * NHD];
__device__ float g_k[NB * NH * NT * NHD];
__device__ float g_v[NB * NH * NT * NHD];
__device__ float g_ctx[NB * NT * ND];
__device__ __align__(256) __nv_bfloat16 g_ahi[BT * ND];      // x or ctx, hi part
__device__ __align__(256) __nv_bfloat16 g_alo[BT * ND];      // x or ctx, lo part
__device__ __align__(256) __nv_bfloat16 g_wthi[4 * ND * ND]; // W^T hi (q,k,v,o)
__device__ __align__(256) __nv_bfloat16 g_wtlo[4 * ND * ND]; // W^T lo

// ---------------- PTX helpers --------------------------------------------
#define CP_ASYNC16(smem, gmem) \
    asm volatile("cp.async.cg.shared.global [%0], [%1], 16;" :: "r"(smem), "l"(gmem))
#define CP_COMMIT()  asm volatile("cp.async.commit_group;" ::: "memory")
#define CP_WAIT(n)   asm volatile("cp.async.wait_group %0;" :: "n"(n) : "memory")

__device__ __forceinline__ void ldsm4(uint32_t& r0, uint32_t& r1, uint32_t& r2,
                                      uint32_t& r3, uint32_t addr) {
    asm volatile("ldmatrix.sync.aligned.m8n8.x4.shared.b16 {%0,%1,%2,%3}, [%4];"
                 : "=r"(r0), "=r"(r1), "=r"(r2), "=r"(r3) : "r"(addr));
}
__device__ __forceinline__ void mma16816(float* c, const uint32_t* a,
                                         const uint32_t* b) {
    asm volatile(
        "mma.sync.aligned.m16n8k16.row.col.f32.bf16.bf16.f32 "
        "{%0,%1,%2,%3}, {%4,%5,%6,%7}, {%8,%9}, {%0,%1,%2,%3};"
        : "+f"(c[0]), "+f"(c[1]), "+f"(c[2]), "+f"(c[3])
        : "r"(a[0]), "r"(a[1]), "r"(a[2]), "r"(a[3]), "r"(b[0]), "r"(b[1]));
}

// ---------------- conversion kernels -------------------------------------
__global__ __launch_bounds__(256) void split4_kernel(
    const float* __restrict__ in, __nv_bfloat16* __restrict__ hi,
    __nv_bfloat16* __restrict__ lo, int n4)
{
    int i = blockIdx.x * 256 + threadIdx.x;
    if (i >= n4) return;
    float4 v = ((const float4*)in)[i];
    __nv_bfloat16 h0 = __float2bfloat16(v.x), h1 = __float2bfloat16(v.y);
    __nv_bfloat16 h2 = __float2bfloat16(v.z), h3 = __float2bfloat16(v.w);
    __nv_bfloat16 l0 = __float2bfloat16(v.x - __bfloat162float(h0));
    __nv_bfloat16 l1 = __float2bfloat16(v.y - __bfloat162float(h1));
    __nv_bfloat16 l2 = __float2bfloat16(v.z - __bfloat162float(h2));
    __nv_bfloat16 l3 = __float2bfloat16(v.w - __bfloat162float(h3));
    __nv_bfloat162* ph = (__nv_bfloat162*)hi;
    __nv_bfloat162* pl = (__nv_bfloat162*)lo;
    ph[i * 2]     = __nv_bfloat162(h0, h1);
    ph[i * 2 + 1] = __nv_bfloat162(h2, h3);
    pl[i * 2]     = __nv_bfloat162(l0, l1);
    pl[i * 2 + 1] = __nv_bfloat162(l2, l3);
}

// W[k][n] -> Wt[n][k] split into bf16 hi/lo. grid (24,24), block (32,8).
__global__ void wsplit_kernel(const float* __restrict__ W,
                              __nv_bfloat16* __restrict__ hi,
                              __nv_bfloat16* __restrict__ lo)
{
    __shared__ float t[32][33];
    const int x0 = blockIdx.x * 32;   // n tile
    const int y0 = blockIdx.y * 32;   // k tile
    const int tx = threadIdx.x, ty = threadIdx.y;
#pragma unroll
    for (int r = 0; r < 4; r++)
        t[ty + r * 8][tx] = W[(size_t)(y0 + ty + r * 8) * ND + x0 + tx];
    __syncthreads();
#pragma unroll
    for (int r = 0; r < 4; r++) {
        float v = t[tx][ty + r * 8];
        __nv_bfloat16 h = __float2bfloat16(v);
        __nv_bfloat16 l = __float2bfloat16(v - __bfloat162float(h));
        size_t o = (size_t)(x0 + ty + r * 8) * ND + y0 + tx;
        hi[o] = h; lo[o] = l;
    }
}

// ---------------- mma.sync GEMM -------------------------------------------
// C[65536,768] = (Ahi+Alo)[M,K] x (Bhi+Blo)[N,K]^T, bf16 hi/lo 3-term split.
// CTA tile 128x128, BK=64, 8 warps (2x4), warp tile 64x32, m16n8k16 HMMA.
// Smem per stage: Ahi|Alo|Bhi|Blo, each 128 rows x 128B (XOR-swizzled rows).
#define BK 64
#define KCH (ND / BK)                    // 12
#define TILE_B  16384                    // one 128x64 bf16 tile = 16KB
#define STAGE_B (4 * TILE_B)             // 64KB
#define GEMM_SMEM (2 * STAGE_B)          // 128KB

__device__ __forceinline__ uint32_t swz(int row, int colbytes) {
    return (uint32_t)(row * 128 + (colbytes ^ ((row & 7) * 16)));
}

template <bool PERMUTE, bool BIAS>
__global__ __launch_bounds__(256, 1) void gemm_mma(
    const __nv_bfloat16* __restrict__ Ahi, const __nv_bfloat16* __restrict__ Alo,
    const __nv_bfloat16* __restrict__ Bhi, const __nv_bfloat16* __restrict__ Blo,
    float* __restrict__ C, const float* __restrict__ bias)
{
    extern __shared__ char smem[];
    const uint32_t sb = (uint32_t)__cvta_generic_to_shared(smem);
    const int tid  = threadIdx.x;
    const int wid  = tid >> 5;
    const int lane = tid & 31;
    const int bx = blockIdx.x, by = blockIdx.y;
    const int wm = wid >> 2;          // 0..1  (M)
    const int wn = wid & 3;           // 0..3  (N)

    const size_t aRow = (size_t)by * 128;
    const size_t bRow = (size_t)bx * 128;

    // cp.async indexing: 256 threads x 4 row-quarters cover 128 rows x 8 chunks.
    const int ldrow = tid >> 3;       // 0..31, +q*32 covers 0..127
    const int ldck  = tid & 7;        // 16B chunk within 128B row

    auto load_chunk = [&](int c, int s) {
        const int kb = c * BK;
        const uint32_t base = sb + s * STAGE_B;
#pragma unroll
        for (int q = 0; q < 4; q++) {
            const int row = ldrow + q * 32;
            const uint32_t so = swz(row, ldck * 16);
            const size_t goa = (aRow + row) * ND + kb + ldck * 8;
            const size_t gob = (bRow + row) * ND + kb + ldck * 8;
            CP_ASYNC16(base + 0 * TILE_B + so, Ahi + goa);
            CP_ASYNC16(base + 1 * TILE_B + so, Alo + goa);
            CP_ASYNC16(base + 2 * TILE_B + so, Bhi + gob);
            CP_ASYNC16(base + 3 * TILE_B + so, Blo + gob);
        }
        CP_COMMIT();
    };

    // ldmatrix per-lane address pieces.
    // A x4 (one m16k16 frag): row = m0 + ((l>>3)&1)*8 + (l&7), k8 = (l>>4)*8
    const int a_rofs = ((lane >> 3) & 1) * 8 + (lane & 7);
    const int a_k8   = (lane >> 4) * 8;
    // B x4 (two n8k16 frags): row = n0 + (l>>4)*8 + (l&7), k8 = ((l>>3)&1)*8
    const int b_rofs = (lane >> 4) * 8 + (lane & 7);
    const int b_k8   = ((lane >> 3) & 1) * 8;

    float acc[4][4][4];
#pragma unroll
    for (int mt = 0; mt < 4; mt++)
#pragma unroll
        for (int nt = 0; nt < 4; nt++)
#pragma unroll
            for (int e = 0; e < 4; e++) acc[mt][nt][e] = 0.f;

    load_chunk(0, 0);

    for (int c = 0; c < KCH; c++) {
        const int s = c & 1;
        if (c + 1 < KCH) { load_chunk(c + 1, s ^ 1); CP_WAIT(1); }
        else             { CP_WAIT(0); }
        __syncthreads();

        const uint32_t base = sb + s * STAGE_B;
#pragma unroll
        for (int ks = 0; ks < 4; ks++) {
            uint32_t ah[4][4], al[4][4], bh[4][2], bl[4][2];
#pragma unroll
            for (int mt = 0; mt < 4; mt++) {
                const int row = wm * 64 + mt * 16 + a_rofs;
                const uint32_t so = swz(row, (ks * 16 + a_k8) * 2);
                ldsm4(ah[mt][0], ah[mt][1], ah[mt][2], ah[mt][3],
                      base + 0 * TILE_B + so);
                ldsm4(al[mt][0], al[mt][1], al[mt][2], al[mt][3],
                      base + 1 * TILE_B + so);
            }
#pragma unroll
            for (int p = 0; p < 2; p++) {
                const int row = wn * 32 + p * 16 + b_rofs;
                const uint32_t so = swz(row, (ks * 16 + b_k8) * 2);
                ldsm4(bh[2 * p][0], bh[2 * p][1], bh[2 * p + 1][0], bh[2 * p + 1][1],
                      base + 2 * TILE_B + so);
                ldsm4(bl[2 * p][0], bl[2 * p][1], bl[2 * p + 1][0], bl[2 * p + 1][1],
                      base + 3 * TILE_B + so);
            }
#pragma unroll
            for (int mt = 0; mt < 4; mt++)
#pragma unroll
                for (int nt = 0; nt < 4; nt++) {
                    mma16816(acc[mt][nt], ah[mt], bh[nt]);
                    mma16816(acc[mt][nt], ah[mt], bl[nt]);
                    mma16816(acc[mt][nt], al[mt], bh[nt]);
                }
        }
        __syncthreads();
    }

    // Epilogue. Lane g = lane>>2 (row), t = lane&3 (col pair).
    const int g = lane >> 2, t = lane & 3;
#pragma unroll
    for (int mt = 0; mt < 4; mt++) {
#pragma unroll
        for (int nt = 0; nt < 4; nt++) {
            const int col  = wn * 32 + nt * 8 + t * 2;
            const int gcol = bx * 128 + col;
#pragma unroll
            for (int half = 0; half < 2; half++) {
                const int row = wm * 64 + mt * 16 + g + half * 8;
                float2 v = make_float2(acc[mt][nt][half * 2],
                                       acc[mt][nt][half * 2 + 1]);
                if (PERMUTE) {
                    const int h = gcol >> 6, d = gcol & 63;
                    *(float2*)(C + ((size_t)(by * NH + h) * NT + row) * NHD + d) = v;
                } else {
                    if (BIAS) { v.x += bias[gcol]; v.y += bias[gcol + 1]; }
                    *(float2*)(C + (size_t)(by * 128 + row) * ND + gcol) = v;
                }
            }
        }
    }
}

// ---------------- fused attention (fp32, proven correct) ------------------
#define QT_STRIDE 132
#define V_STRIDE  68
#define ST_STRIDE 132
#define ATTN_SMEM ((64 * QT_STRIDE * 2 + 128 * V_STRIDE + 128 * ST_STRIDE) * 4)

__global__ __launch_bounds__(256, 1) void attn_kernel(
    const float* __restrict__ q, const float* __restrict__ k,
    const float* __restrict__ v, float* __restrict__ ctx)
{
    extern __shared__ float sm[];
    float* Qt = sm;
    float* Kt = Qt + 64 * QT_STRIDE;
    float* Vs = Kt + 64 * QT_STRIDE;
    float* St = Vs + 128 * V_STRIDE;

    const int tid = threadIdx.x;
    const int bh  = blockIdx.x;
    const int b   = bh / NH;
    const int h   = bh - b * NH;
    const size_t base = (size_t)bh * (NT * NHD);

    const float4* q4 = (const float4*)(q + base);
    const float4* k4 = (const float4*)(k + base);
    const float4* v4 = (const float4*)(v + base);

    for (int idx = tid; idx < 2048; idx += 256) {
        const int row = idx >> 4;
        const int d   = (idx & 15) << 2;
        float4 aq = q4[idx];
        float4 ak = k4[idx];
        float4 av = v4[idx];
        Qt[(d + 0) * QT_STRIDE + row] = aq.x;
        Qt[(d + 1) * QT_STRIDE + row] = aq.y;
        Qt[(d + 2) * QT_STRIDE + row] = aq.z;
        Qt[(d + 3) * QT_STRIDE + row] = aq.w;
        Kt[(d + 0) * QT_STRIDE + row] = ak.x;
        Kt[(d + 1) * QT_STRIDE + row] = ak.y;
        Kt[(d + 2) * QT_STRIDE + row] = ak.z;
        Kt[(d + 3) * QT_STRIDE + row] = ak.w;
        *(float4*)&Vs[row * V_STRIDE + d] = av;
    }
    __syncthreads();

    const int ty = tid >> 4, tx = tid & 15;
    const int i0 = ty * 8, j0 = tx * 8;

    {
        float acc[8][8];
#pragma unroll
        for (int i = 0; i < 8; i++)
#pragma unroll
            for (int j = 0; j < 8; j++) acc[i][j] = 0.f;

        for (int d = 0; d < 64; d++) {
            float a[8], bb[8];
            *(float4*)(a     ) = *(const float4*)&Qt[d * QT_STRIDE + i0];
            *(float4*)(a + 4 ) = *(const float4*)&Qt[d * QT_STRIDE + i0 + 4];
            *(float4*)(bb    ) = *(const float4*)&Kt[d * QT_STRIDE + j0];
            *(float4*)(bb + 4) = *(const float4*)&Kt[d * QT_STRIDE + j0 + 4];
#pragma unroll
            for (int i = 0; i < 8; i++)
#pragma unroll
                for (int j = 0; j < 8; j++)
                    acc[i][j] = fmaf(a[i], bb[j], acc[i][j]);
        }
#pragma unroll
        for (int j = 0; j < 8; j++)
#pragma unroll
            for (int i = 0; i < 8; i++)
                St[(j0 + j) * ST_STRIDE + (i0 + i)] = acc[i][j];
    }
    __syncthreads();

    if (tid < 128) {
        const int i = tid;
        const float scale = 0.125f;
        float m = -1e30f;
        for (int j = 0; j <= i; j++) {
            float s = St[j * ST_STRIDE + i] * scale;
            m = fmaxf(m, s);
        }
        float sum = 0.f;
        for (int j = 0; j <= i; j++) {
            float e = __expf(St[j * ST_STRIDE + i] * scale - m);
            St[j * ST_STRIDE + i] = e;
            sum += e;
        }
        for (int j = i + 1; j < 128; j++) St[j * ST_STRIDE + i] = 0.f;
        const float inv = 1.f / sum;
        for (int j = 0; j <= i; j++) St[j * ST_STRIDE + i] *= inv;
    }
    __syncthreads();

    {
        const int d0 = tx << 2;
        float acc[8][4];
#pragma unroll
        for (int i = 0; i < 8; i++)
#pragma unroll
            for (int d = 0; d < 4; d++) acc[i][d] = 0.f;

        for (int j = 0; j < 128; j++) {
            float a[8], bb[4];
            *(float4*)(a    ) = *(const float4*)&St[j * ST_STRIDE + i0];
            *(float4*)(a + 4) = *(const float4*)&St[j * ST_STRIDE + i0 + 4];
            *(float4*)(bb   ) = *(const float4*)&Vs[j * V_STRIDE + d0];
#pragma unroll
            for (int i = 0; i < 8; i++)
#pragma unroll
                for (int d = 0; d < 4; d++)
                    acc[i][d] = fmaf(a[i], bb[d], acc[i][d]);
        }
#pragma unroll
        for (int i = 0; i < 8; i++) {
            const size_t addr = ((size_t)(b * NT + i0 + i)) * ND + h * NHD + d0;
            *(float4*)&ctx[addr] = make_float4(acc[i][0], acc[i][1], acc[i][2], acc[i][3]);
        }
    }
}

// ---------------- launch ---------------------------------------------------
extern "C" void kernel_launch(void* const* d_in, const int* in_sizes, int n_in,
                              void* d_out, int out_size)
{
    const float* x  = (const float*)d_in[0];
    const float* Wq = (const float*)d_in[1];
    const float* Wk = (const float*)d_in[2];
    const float* Wv = (const float*)d_in[3];
    const float* Wo = (const float*)d_in[4];
    const float* bo = (const float*)d_in[5];
    float* out = (float*)d_out;

    void *pq, *pk, *pv, *pctx, *pahi, *palo, *pwthi, *pwtlo;
    cudaGetSymbolAddress(&pq,   g_q);
    cudaGetSymbolAddress(&pk,   g_k);
    cudaGetSymbolAddress(&pv,   g_v);
    cudaGetSymbolAddress(&pctx, g_ctx);
    cudaGetSymbolAddress(&pahi, g_ahi);
    cudaGetSymbolAddress(&palo, g_alo);
    cudaGetSymbolAddress(&pwthi, g_wthi);
    cudaGetSymbolAddress(&pwtlo, g_wtlo);
    __nv_bfloat16* ahi  = (__nv_bfloat16*)pahi;
    __nv_bfloat16* alo  = (__nv_bfloat16*)palo;
    __nv_bfloat16* wthi = (__nv_bfloat16*)pwthi;
    __nv_bfloat16* wtlo = (__nv_bfloat16*)pwtlo;

    cudaFuncSetAttribute(gemm_mma<true, false>,
                         cudaFuncAttributeMaxDynamicSharedMemorySize, GEMM_SMEM);
    cudaFuncSetAttribute(gemm_mma<false, true>,
                         cudaFuncAttributeMaxDynamicSharedMemorySize, GEMM_SMEM);
    cudaFuncSetAttribute(attn_kernel,
                         cudaFuncAttributeMaxDynamicSharedMemorySize, ATTN_SMEM);

    const int n4 = BT * ND / 4;
    dim3 wgrid(ND / 32, ND / 32);       // (24,24)
    dim3 wblk(32, 8);
    dim3 ggrid(ND / 128, BT / 128);     // (6,512)

    // 1) split x -> bf16 hi/lo
    split4_kernel<<<(n4 + 255) / 256, 256>>>(x, ahi, alo, n4);
    // 2) transpose+split all weights
    wsplit_kernel<<<wgrid, wblk>>>(Wq, wthi + 0 * ND * ND, wtlo + 0 * ND * ND);
    wsplit_kernel<<<wgrid, wblk>>>(Wk, wthi + 1 * ND * ND, wtlo + 1 * ND * ND);
    wsplit_kernel<<<wgrid, wblk>>>(Wv, wthi + 2 * ND * ND, wtlo + 2 * ND * ND);
    wsplit_kernel<<<wgrid, wblk>>>(Wo, wthi + 3 * ND * ND, wtlo + 3 * ND * ND);
    // 3) Q/K/V projections (HMMA, permuted output)
    gemm_mma<true, false><<<ggrid, 256, GEMM_SMEM>>>(ahi, alo,
        wthi + 0 * ND * ND, wtlo + 0 * ND * ND, (float*)pq, nullptr);
    gemm_mma<true, false><<<ggrid, 256, GEMM_SMEM>>>(ahi, alo,
        wthi + 1 * ND * ND, wtlo + 1 * ND * ND, (float*)pk, nullptr);
    gemm_mma<true, false><<<ggrid, 256, GEMM_SMEM>>>(ahi, alo,
        wthi + 2 * ND * ND, wtlo + 2 * ND * ND, (float*)pv, nullptr);
    // 4) attention
    attn_kernel<<<NB * NH, 256, ATTN_SMEM>>>((const float*)pq, (const float*)pk,
                                             (const float*)pv, (float*)pctx);
    // 5) split ctx, output projection with bias
    split4_kernel<<<(n4 + 255) / 256, 256>>>((const float*)pctx, ahi, alo, n4);
    gemm_mma<false, true><<<ggrid, 256, GEMM_SMEM>>>(ahi, alo,
        wthi + 3 * ND * ND, wtlo + 3 * ND * ND, out, bo);
}

// round 6
// speedup vs baseline: 3.6866x; 1.1651x over previous
#include <cuda_runtime.h>
#include <cuda_bf16.h>
#include <cstdint>

// Problem: x[512,128,768] fp32; Wq/k/v/o [768,768]; bo[768]; out[512,128,768] fp32.
#define NB   512
#define NT   128
#define ND   768
#define NH   12
#define NHD  64
#define BT   (NB * NT)          // 65536

// ---------------- scratch ----------------
__device__ float g_q[NB * NH * NT * NHD];
__device__ float g_k[NB * NH * NT * NHD];
__device__ float g_v[NB * NH * NT * NHD];
__device__ float g_ctx[NB * NT * ND];
__device__ __align__(256) __nv_bfloat16 g_ahi[BT * ND];
__device__ __align__(256) __nv_bfloat16 g_alo[BT * ND];
__device__ __align__(256) __nv_bfloat16 g_wthi[4 * ND * ND]; // W^T hi (q,k,v,o) -> qkv contiguous [2304][768]
__device__ __align__(256) __nv_bfloat16 g_wtlo[4 * ND * ND];

// ---------------- PTX helpers ----------------
#define CP_ASYNC16(smem, gmem) \
    asm volatile("cp.async.cg.shared.global [%0], [%1], 16;" :: "r"(smem), "l"(gmem))
#define CP_COMMIT()  asm volatile("cp.async.commit_group;" ::: "memory")
#define CP_WAIT(n)   asm volatile("cp.async.wait_group %0;" :: "n"(n) : "memory")

__device__ __forceinline__ void ldsm4(uint32_t& r0, uint32_t& r1, uint32_t& r2,
                                      uint32_t& r3, uint32_t addr) {
    asm volatile("ldmatrix.sync.aligned.m8n8.x4.shared.b16 {%0,%1,%2,%3}, [%4];"
                 : "=r"(r0), "=r"(r1), "=r"(r2), "=r"(r3) : "r"(addr));
}
__device__ __forceinline__ void mma16816(float* c, const uint32_t* a,
                                         const uint32_t* b) {
    asm volatile(
        "mma.sync.aligned.m16n8k16.row.col.f32.bf16.bf16.f32 "
        "{%0,%1,%2,%3}, {%4,%5,%6,%7}, {%8,%9}, {%0,%1,%2,%3};"
        : "+f"(c[0]), "+f"(c[1]), "+f"(c[2]), "+f"(c[3])
        : "r"(a[0]), "r"(a[1]), "r"(a[2]), "r"(a[3]), "r"(b[0]), "r"(b[1]));
}
__device__ __forceinline__ void split1(float v, __nv_bfloat16& h, __nv_bfloat16& l) {
    h = __float2bfloat16(v);
    l = __float2bfloat16(v - __bfloat162float(h));
}
__device__ __forceinline__ uint32_t pk2(__nv_bfloat16 a, __nv_bfloat16 b) {
    __nv_bfloat162 t = __halves2bfloat162(a, b);
    return *(uint32_t*)&t;
}

// ---------------- conversion kernels ----------------
__global__ __launch_bounds__(256) void split4_kernel(
    const float* __restrict__ in, __nv_bfloat16* __restrict__ hi,
    __nv_bfloat16* __restrict__ lo, int n4)
{
    int i = blockIdx.x * 256 + threadIdx.x;
    if (i >= n4) return;
    float4 v = ((const float4*)in)[i];
    __nv_bfloat16 h0, h1, h2, h3, l0, l1, l2, l3;
    split1(v.x, h0, l0); split1(v.y, h1, l1);
    split1(v.z, h2, l2); split1(v.w, h3, l3);
    ((uint32_t*)hi)[i * 2]     = pk2(h0, h1);
    ((uint32_t*)hi)[i * 2 + 1] = pk2(h2, h3);
    ((uint32_t*)lo)[i * 2]     = pk2(l0, l1);
    ((uint32_t*)lo)[i * 2 + 1] = pk2(l2, l3);
}

// W[k][n] -> Wt[n][k] split into bf16 hi/lo. grid (24,24), block (32,8).
__global__ void wsplit_kernel(const float* __restrict__ W,
                              __nv_bfloat16* __restrict__ hi,
                              __nv_bfloat16* __restrict__ lo)
{
    __shared__ float t[32][33];
    const int x0 = blockIdx.x * 32;
    const int y0 = blockIdx.y * 32;
    const int tx = threadIdx.x, ty = threadIdx.y;
#pragma unroll
    for (int r = 0; r < 4; r++)
        t[ty + r * 8][tx] = W[(size_t)(y0 + ty + r * 8) * ND + x0 + tx];
    __syncthreads();
#pragma unroll
    for (int r = 0; r < 4; r++) {
        float v = t[tx][ty + r * 8];
        __nv_bfloat16 h, l;
        split1(v, h, l);
        size_t o = (size_t)(x0 + ty + r * 8) * ND + y0 + tx;
        hi[o] = h; lo[o] = l;
    }
}

// ---------------- mma.sync GEMM (3-stage pipeline) ----------------
// MODE 0: QKV merged — B is [2304][768], outputs to o0/o1/o2 permuted [b,h,t,hd].
// MODE 1: Wo — B is [768][768], output o0 row-major + bias.
#define BK 64
#define KCH (ND / BK)                    // 12
#define TILE_B  16384
#define STAGE_B (4 * TILE_B)             // 64KB
#define GEMM_SMEM (3 * STAGE_B)          // 192KB

__device__ __forceinline__ uint32_t swz(int row, int colbytes) {
    return (uint32_t)(row * 128 + (colbytes ^ ((row & 7) * 16)));
}

template <int MODE>
__global__ __launch_bounds__(256, 1) void gemm_mma(
    const __nv_bfloat16* __restrict__ Ahi, const __nv_bfloat16* __restrict__ Alo,
    const __nv_bfloat16* __restrict__ Bhi, const __nv_bfloat16* __restrict__ Blo,
    float* __restrict__ o0, float* __restrict__ o1, float* __restrict__ o2,
    const float* __restrict__ bias)
{
    extern __shared__ char smem[];
    const uint32_t sb = (uint32_t)__cvta_generic_to_shared(smem);
    const int tid  = threadIdx.x;
    const int wid  = tid >> 5;
    const int lane = tid & 31;
    const int bx = blockIdx.x, by = blockIdx.y;
    const int wm = wid >> 2;
    const int wn = wid & 3;

    const size_t aRow = (size_t)by * 128;
    const size_t bRow = (size_t)bx * 128;

    const int ldrow = tid >> 3;
    const int ldck  = tid & 7;

    auto load_chunk = [&](int c, int s) {
        const int kb = c * BK;
        const uint32_t base = sb + s * STAGE_B;
#pragma unroll
        for (int q = 0; q < 4; q++) {
            const int row = ldrow + q * 32;
            const uint32_t so = swz(row, ldck * 16);
            const size_t goa = (aRow + row) * ND + kb + ldck * 8;
            const size_t gob = (bRow + row) * ND + kb + ldck * 8;
            CP_ASYNC16(base + 0 * TILE_B + so, Ahi + goa);
            CP_ASYNC16(base + 1 * TILE_B + so, Alo + goa);
            CP_ASYNC16(base + 2 * TILE_B + so, Bhi + gob);
            CP_ASYNC16(base + 3 * TILE_B + so, Blo + gob);
        }
        CP_COMMIT();
    };

    const int a_rofs = ((lane >> 3) & 1) * 8 + (lane & 7);
    const int a_k8   = (lane >> 4) * 8;
    const int b_rofs = (lane >> 4) * 8 + (lane & 7);
    const int b_k8   = ((lane >> 3) & 1) * 8;

    float acc[4][4][4];
#pragma unroll
    for (int mt = 0; mt < 4; mt++)
#pragma unroll
        for (int nt = 0; nt < 4; nt++)
#pragma unroll
            for (int e = 0; e < 4; e++) acc[mt][nt][e] = 0.f;

    load_chunk(0, 0);
    load_chunk(1, 1);

    for (int c = 0; c < KCH; c++) {
        if (c < KCH - 1) { CP_WAIT(1); } else { CP_WAIT(0); }
        __syncthreads();

        const uint32_t base = sb + (c % 3) * STAGE_B;
#pragma unroll
        for (int ks = 0; ks < 4; ks++) {
            uint32_t ah[4][4], al[4][4], bh[4][2], bl[4][2];
#pragma unroll
            for (int mt = 0; mt < 4; mt++) {
                const int row = wm * 64 + mt * 16 + a_rofs;
                const uint32_t so = swz(row, (ks * 16 + a_k8) * 2);
                ldsm4(ah[mt][0], ah[mt][1], ah[mt][2], ah[mt][3],
                      base + 0 * TILE_B + so);
                ldsm4(al[mt][0], al[mt][1], al[mt][2], al[mt][3],
                      base + 1 * TILE_B + so);
            }
#pragma unroll
            for (int p = 0; p < 2; p++) {
                const int row = wn * 32 + p * 16 + b_rofs;
                const uint32_t so = swz(row, (ks * 16 + b_k8) * 2);
                ldsm4(bh[2 * p][0], bh[2 * p][1], bh[2 * p + 1][0], bh[2 * p + 1][1],
                      base + 2 * TILE_B + so);
                ldsm4(bl[2 * p][0], bl[2 * p][1], bl[2 * p + 1][0], bl[2 * p + 1][1],
                      base + 3 * TILE_B + so);
            }
#pragma unroll
            for (int mt = 0; mt < 4; mt++)
#pragma unroll
                for (int nt = 0; nt < 4; nt++) {
                    mma16816(acc[mt][nt], ah[mt], bh[nt]);
                    mma16816(acc[mt][nt], ah[mt], bl[nt]);
                    mma16816(acc[mt][nt], al[mt], bh[nt]);
                }
        }
        if (c + 2 < KCH) load_chunk(c + 2, (c + 2) % 3);
    }

    // Epilogue
    const int g = lane >> 2, t = lane & 3;
    float* dst = o0;
    int within0 = 0;
    if (MODE == 0) {
        const int tensor = bx / 6;
        dst = (tensor == 0) ? o0 : ((tensor == 1) ? o1 : o2);
        within0 = (bx % 6) * 128;
    }
#pragma unroll
    for (int mt = 0; mt < 4; mt++) {
#pragma unroll
        for (int nt = 0; nt < 4; nt++) {
            const int col = wn * 32 + nt * 8 + t * 2;
#pragma unroll
            for (int half = 0; half < 2; half++) {
                const int row = wm * 64 + mt * 16 + g + half * 8;
                float2 v = make_float2(acc[mt][nt][half * 2],
                                       acc[mt][nt][half * 2 + 1]);
                if (MODE == 0) {
                    const int wc = within0 + col;
                    const int h = wc >> 6, d = wc & 63;
                    *(float2*)(dst + ((size_t)(by * NH + h) * NT + row) * NHD + d) = v;
                } else {
                    const int gcol = bx * 128 + col;
                    v.x += bias[gcol]; v.y += bias[gcol + 1];
                    *(float2*)(dst + (size_t)(by * 128 + row) * ND + gcol) = v;
                }
            }
        }
    }
}

// ---------------- tensor-core attention ----------------
// One CTA per (b,h). T=128, hd=64. 8 warps (2x4).
// Smem (byte offsets):
//   QHI 0, QLO 18432, KHI 36864, KLO 55296      (128 rows x 72 bf16, stride 144B)
//   PHI 0, PLO 36864  (union over Q/K after S)  (128 rows x 136 bf16, stride 272B)
//   VTHI 73728, VTLO 91136                      (64 rows x 136 bf16, stride 272B)
//   S 108544 (fp32, 128 rows x 134, stride 536B)
#define AQ_HI 0
#define AQ_LO 18432
#define AK_HI 36864
#define AK_LO 55296
#define AP_HI 0
#define AP_LO 36864
#define AV_HI 73728
#define AV_LO 91136
#define AS_F  108544
#define ATTN_SMEM 177152

__global__ __launch_bounds__(256, 1) void attn_tc(
    const float* __restrict__ q, const float* __restrict__ k,
    const float* __restrict__ v, float* __restrict__ ctx)
{
    extern __shared__ char sm[];
    const uint32_t sb = (uint32_t)__cvta_generic_to_shared(sm);
    const int tid  = threadIdx.x;
    const int wid  = tid >> 5;
    const int lane = tid & 31;
    const int bh = blockIdx.x;
    const int b  = bh / NH;
    const int h  = bh - b * NH;
    const int wm = wid >> 2;       // 0..1
    const int wn = wid & 3;        // 0..3

    const size_t base = (size_t)bh * (NT * NHD);
    const float4* q4 = (const float4*)(q + base);
    const float4* k4 = (const float4*)(k + base);
    const float4* v4 = (const float4*)(v + base);
    float* S = (float*)(sm + AS_F);

    // ---- load + convert Q,K (hi/lo, stride 72 bf16) and V transposed ----
    for (int idx = tid; idx < 2048; idx += 256) {
        const int row = idx >> 4;
        const int c4  = (idx & 15) << 2;
        float4 a = q4[idx];
        __nv_bfloat16 h0, h1, h2, h3, l0, l1, l2, l3;
        split1(a.x, h0, l0); split1(a.y, h1, l1);
        split1(a.z, h2, l2); split1(a.w, h3, l3);
        *(uint2*)(sm + AQ_HI + row * 144 + c4 * 2) =
            make_uint2(pk2(h0, h1), pk2(h2, h3));
        *(uint2*)(sm + AQ_LO + row * 144 + c4 * 2) =
            make_uint2(pk2(l0, l1), pk2(l2, l3));
        a = k4[idx];
        split1(a.x, h0, l0); split1(a.y, h1, l1);
        split1(a.z, h2, l2); split1(a.w, h3, l3);
        *(uint2*)(sm + AK_HI + row * 144 + c4 * 2) =
            make_uint2(pk2(h0, h1), pk2(h2, h3));
        *(uint2*)(sm + AK_LO + row * 144 + c4 * 2) =
            make_uint2(pk2(l0, l1), pk2(l2, l3));
        a = v4[idx];                 // V[j=row][d=c4..c4+3] -> VT[d][j]
        split1(a.x, h0, l0); split1(a.y, h1, l1);
        split1(a.z, h2, l2); split1(a.w, h3, l3);
        __nv_bfloat16* vh = (__nv_bfloat16*)(sm + AV_HI);
        __nv_bfloat16* vl = (__nv_bfloat16*)(sm + AV_LO);
        vh[(c4 + 0) * 136 + row] = h0; vl[(c4 + 0) * 136 + row] = l0;
        vh[(c4 + 1) * 136 + row] = h1; vl[(c4 + 1) * 136 + row] = l1;
        vh[(c4 + 2) * 136 + row] = h2; vl[(c4 + 2) * 136 + row] = l2;
        vh[(c4 + 3) * 136 + row] = h3; vl[(c4 + 3) * 136 + row] = l3;
    }
    __syncthreads();

    const int a_rofs = ((lane >> 3) & 1) * 8 + (lane & 7);
    const int a_k8   = (lane >> 4) * 8;
    const int b_rofs = (lane >> 4) * 8 + (lane & 7);
    const int b_k8   = ((lane >> 3) & 1) * 8;
    const int g = lane >> 2, t = lane & 3;

    // ---- S = Q K^T (M=128,N=128,K=64), skip fully-masked tiles ----
    const bool skip = (wm == 0 && wn >= 2);   // rows<64, cols>=64: all masked
    if (!skip) {
        float acc[4][4][4];
#pragma unroll
        for (int mt = 0; mt < 4; mt++)
#pragma unroll
            for (int nt = 0; nt < 4; nt++)
#pragma unroll
                for (int e = 0; e < 4; e++) acc[mt][nt][e] = 0.f;

#pragma unroll
        for (int ks = 0; ks < 4; ks++) {
            uint32_t ah[4][4], al[4][4], bh[4][2], bl[4][2];
#pragma unroll
            for (int mt = 0; mt < 4; mt++) {
                const int row = wm * 64 + mt * 16 + a_rofs;
                const uint32_t off = row * 144 + (ks * 16 + a_k8) * 2;
                ldsm4(ah[mt][0], ah[mt][1], ah[mt][2], ah[mt][3], sb + AQ_HI + off);
                ldsm4(al[mt][0], al[mt][1], al[mt][2], al[mt][3], sb + AQ_LO + off);
            }
#pragma unroll
            for (int p = 0; p < 2; p++) {
                const int row = wn * 32 + p * 16 + b_rofs;
                const uint32_t off = row * 144 + (ks * 16 + b_k8) * 2;
                ldsm4(bh[2 * p][0], bh[2 * p][1], bh[2 * p + 1][0], bh[2 * p + 1][1],
                      sb + AK_HI + off);
                ldsm4(bl[2 * p][0], bl[2 * p][1], bl[2 * p + 1][0], bl[2 * p + 1][1],
                      sb + AK_LO + off);
            }
#pragma unroll
            for (int mt = 0; mt < 4; mt++)
#pragma unroll
                for (int nt = 0; nt < 4; nt++) {
                    mma16816(acc[mt][nt], ah[mt], bh[nt]);
                    mma16816(acc[mt][nt], ah[mt], bl[nt]);
                    mma16816(acc[mt][nt], al[mt], bh[nt]);
                }
        }
        // store S (fp32, stride 134)
#pragma unroll
        for (int mt = 0; mt < 4; mt++)
#pragma unroll
            for (int nt = 0; nt < 4; nt++) {
                const int col = wn * 32 + nt * 8 + t * 2;
#pragma unroll
                for (int half = 0; half < 2; half++) {
                    const int row = wm * 64 + mt * 16 + g + half * 8;
                    *(float2*)(S + row * 134 + col) =
                        make_float2(acc[mt][nt][half * 2], acc[mt][nt][half * 2 + 1]);
                }
            }
    }
    __syncthreads();

    // ---- causal softmax (thread per row), write P hi/lo over dead Q/K ----
    if (tid < 128) {
        const int i = tid;
        const float scale = 0.125f;
        float* Srow = S + i * 134;
        float m = -1e30f;
        for (int j = 0; j <= i; j++) m = fmaxf(m, Srow[j]);
        float sum = 0.f;
        for (int j = 0; j <= i; j++) {
            float e = __expf((Srow[j] - m) * scale);
            Srow[j] = e;
            sum += e;
        }
        const float inv = 1.f / sum;
        __nv_bfloat16* ph = (__nv_bfloat16*)(sm + AP_HI) + i * 136;
        __nv_bfloat16* pl = (__nv_bfloat16*)(sm + AP_LO) + i * 136;
        for (int j = 0; j <= i; j++) {
            __nv_bfloat16 hh, ll;
            split1(Srow[j] * inv, hh, ll);
            ph[j] = hh; pl[j] = ll;
        }
        const __nv_bfloat16 z = __float2bfloat16(0.f);
        for (int j = i + 1; j < 128; j++) { ph[j] = z; pl[j] = z; }
    }
    __syncthreads();

    // ---- ctx = P V (M=128,N=64,K=128), warp tile 64x16 ----
    {
        float acc[4][2][4];
#pragma unroll
        for (int mt = 0; mt < 4; mt++)
#pragma unroll
            for (int nt = 0; nt < 2; nt++)
#pragma unroll
                for (int e = 0; e < 4; e++) acc[mt][nt][e] = 0.f;

#pragma unroll
        for (int ks = 0; ks < 8; ks++) {
            uint32_t ph[4][4], pl[4][4], vh[2][2], vl[2][2];
#pragma unroll
            for (int mt = 0; mt < 4; mt++) {
                const int row = wm * 64 + mt * 16 + a_rofs;
                const uint32_t off = row * 272 + (ks * 16 + a_k8) * 2;
                ldsm4(ph[mt][0], ph[mt][1], ph[mt][2], ph[mt][3], sb + AP_HI + off);
                ldsm4(pl[mt][0], pl[mt][1], pl[mt][2], pl[mt][3], sb + AP_LO + off);
            }
            {
                const int row = wn * 16 + b_rofs;
                const uint32_t off = row * 272 + (ks * 16 + b_k8) * 2;
                ldsm4(vh[0][0], vh[0][1], vh[1][0], vh[1][1], sb + AV_HI + off);
                ldsm4(vl[0][0], vl[0][1], vl[1][0], vl[1][1], sb + AV_LO + off);
            }
#pragma unroll
            for (int mt = 0; mt < 4; mt++)
#pragma unroll
                for (int nt = 0; nt < 2; nt++) {
                    mma16816(acc[mt][nt], ph[mt], vh[nt]);
                    mma16816(acc[mt][nt], ph[mt], vl[nt]);
                    mma16816(acc[mt][nt], pl[mt], vh[nt]);
                }
        }
        // write ctx [B,T,D]
#pragma unroll
        for (int mt = 0; mt < 4; mt++)
#pragma unroll
            for (int nt = 0; nt < 2; nt++) {
                const int col = wn * 16 + nt * 8 + t * 2;
#pragma unroll
                for (int half = 0; half < 2; half++) {
                    const int row = wm * 64 + mt * 16 + g + half * 8;
                    *(float2*)(ctx + ((size_t)(b * NT + row)) * ND + h * NHD + col) =
                        make_float2(acc[mt][nt][half * 2], acc[mt][nt][half * 2 + 1]);
                }
            }
    }
}

// ---------------- launch ----------------
extern "C" void kernel_launch(void* const* d_in, const int* in_sizes, int n_in,
                              void* d_out, int out_size)
{
    const float* x  = (const float*)d_in[0];
    const float* Wq = (const float*)d_in[1];
    const float* Wk = (const float*)d_in[2];
    const float* Wv = (const float*)d_in[3];
    const float* Wo = (const float*)d_in[4];
    const float* bo = (const float*)d_in[5];
    float* out = (float*)d_out;

    void *pq, *pk, *pv, *pctx, *pahi, *palo, *pwthi, *pwtlo;
    cudaGetSymbolAddress(&pq,   g_q);
    cudaGetSymbolAddress(&pk,   g_k);
    cudaGetSymbolAddress(&pv,   g_v);
    cudaGetSymbolAddress(&pctx, g_ctx);
    cudaGetSymbolAddress(&pahi, g_ahi);
    cudaGetSymbolAddress(&palo, g_alo);
    cudaGetSymbolAddress(&pwthi, g_wthi);
    cudaGetSymbolAddress(&pwtlo, g_wtlo);
    __nv_bfloat16* ahi  = (__nv_bfloat16*)pahi;
    __nv_bfloat16* alo  = (__nv_bfloat16*)palo;
    __nv_bfloat16* wthi = (__nv_bfloat16*)pwthi;
    __nv_bfloat16* wtlo = (__nv_bfloat16*)pwtlo;

    cudaFuncSetAttribute(gemm_mma<0>,
                         cudaFuncAttributeMaxDynamicSharedMemorySize, GEMM_SMEM);
    cudaFuncSetAttribute(gemm_mma<1>,
                         cudaFuncAttributeMaxDynamicSharedMemorySize, GEMM_SMEM);
    cudaFuncSetAttribute(attn_tc,
                         cudaFuncAttributeMaxDynamicSharedMemorySize, ATTN_SMEM);

    const int n4 = BT * ND / 4;
    dim3 wgrid(ND / 32, ND / 32);
    dim3 wblk(32, 8);

    // 1) split x -> bf16 hi/lo
    split4_kernel<<<(n4 + 255) / 256, 256>>>(x, ahi, alo, n4);
    // 2) transpose+split all weights (qkv slots contiguous -> [2304][768])
    wsplit_kernel<<<wgrid, wblk>>>(Wq, wthi + 0 * ND * ND, wtlo + 0 * ND * ND);
    wsplit_kernel<<<wgrid, wblk>>>(Wk, wthi + 1 * ND * ND, wtlo + 1 * ND * ND);
    wsplit_kernel<<<wgrid, wblk>>>(Wv, wthi + 2 * ND * ND, wtlo + 2 * ND * ND);
    wsplit_kernel<<<wgrid, wblk>>>(Wo, wthi + 3 * ND * ND, wtlo + 3 * ND * ND);
    // 3) merged QKV projection (one launch, N=2304)
    {
        dim3 ggrid(18, BT / 128);
        gemm_mma<0><<<ggrid, 256, GEMM_SMEM>>>(ahi, alo, wthi, wtlo,
            (float*)pq, (float*)pk, (float*)pv, nullptr);
    }
    // 4) tensor-core attention
    attn_tc<<<NB * NH, 256, ATTN_SMEM>>>((const float*)pq, (const float*)pk,
                                         (const float*)pv, (float*)pctx);
    // 5) split ctx, output projection with bias
    split4_kernel<<<(n4 + 255) / 256, 256>>>((const float*)pctx, ahi, alo, n4);
    {
        dim3 ggrid(6, BT / 128);
        gemm_mma<1><<<ggrid, 256, GEMM_SMEM>>>(ahi, alo,
            wthi + 3 * ND * ND, wtlo + 3 * ND * ND, out, nullptr, nullptr, bo);
    }
}

// round 7
// speedup vs baseline: 3.8495x; 1.0442x over previous
#include <cuda_runtime.h>
#include <cuda_bf16.h>
#include <cstdint>

// Problem: x[512,128,768] fp32; Wq/k/v/o [768,768]; bo[768]; out[512,128,768] fp32.
#define NB   512
#define NT   128
#define ND   768
#define NH   12
#define NHD  64
#define BT   (NB * NT)          // 65536
#define HSZ  (NB * NH * NT * NHD)

// ---------------- scratch ----------------
__device__ __align__(256) __nv_bfloat16 g_qhi[HSZ], g_qlo[HSZ];   // [b,h,t,hd]
__device__ __align__(256) __nv_bfloat16 g_khi[HSZ], g_klo[HSZ];   // [b,h,t,hd]
__device__ __align__(256) __nv_bfloat16 g_vthi[HSZ], g_vtlo[HSZ]; // [b,h,hd,t]
__device__ __align__(256) __nv_bfloat16 g_ahi[BT * ND];           // x-split, then ctx-split
__device__ __align__(256) __nv_bfloat16 g_alo[BT * ND];
__device__ __align__(256) __nv_bfloat16 g_wthi[4 * ND * ND];      // W^T hi (q,k,v,o)
__device__ __align__(256) __nv_bfloat16 g_wtlo[4 * ND * ND];

// ---------------- PTX helpers ----------------
#define CP_ASYNC16(smem, gmem) \
    asm volatile("cp.async.cg.shared.global [%0], [%1], 16;" :: "r"(smem), "l"(gmem))
#define CP_COMMIT()  asm volatile("cp.async.commit_group;" ::: "memory")
#define CP_WAIT(n)   asm volatile("cp.async.wait_group %0;" :: "n"(n) : "memory")

__device__ __forceinline__ void ldsm4(uint32_t& r0, uint32_t& r1, uint32_t& r2,
                                      uint32_t& r3, uint32_t addr) {
    asm volatile("ldmatrix.sync.aligned.m8n8.x4.shared.b16 {%0,%1,%2,%3}, [%4];"
                 : "=r"(r0), "=r"(r1), "=r"(r2), "=r"(r3) : "r"(addr));
}
__device__ __forceinline__ void mma16816(float* c, const uint32_t* a,
                                         const uint32_t* b) {
    asm volatile(
        "mma.sync.aligned.m16n8k16.row.col.f32.bf16.bf16.f32 "
        "{%0,%1,%2,%3}, {%4,%5,%6,%7}, {%8,%9}, {%0,%1,%2,%3};"
        : "+f"(c[0]), "+f"(c[1]), "+f"(c[2]), "+f"(c[3])
        : "r"(a[0]), "r"(a[1]), "r"(a[2]), "r"(a[3]), "r"(b[0]), "r"(b[1]));
}
__device__ __forceinline__ void split1(float v, __nv_bfloat16& h, __nv_bfloat16& l) {
    h = __float2bfloat16(v);
    l = __float2bfloat16(v - __bfloat162float(h));
}
__device__ __forceinline__ uint32_t pk2(__nv_bfloat16 a, __nv_bfloat16 b) {
    __nv_bfloat162 t = __halves2bfloat162(a, b);
    return *(uint32_t*)&t;
}

// ---------------- conversion kernels ----------------
__global__ __launch_bounds__(256) void split4_kernel(
    const float* __restrict__ in, __nv_bfloat16* __restrict__ hi,
    __nv_bfloat16* __restrict__ lo, int n4)
{
    int i = blockIdx.x * 256 + threadIdx.x;
    if (i >= n4) return;
    float4 v = ((const float4*)in)[i];
    __nv_bfloat16 h0, h1, h2, h3, l0, l1, l2, l3;
    split1(v.x, h0, l0); split1(v.y, h1, l1);
    split1(v.z, h2, l2); split1(v.w, h3, l3);
    ((uint32_t*)hi)[i * 2]     = pk2(h0, h1);
    ((uint32_t*)hi)[i * 2 + 1] = pk2(h2, h3);
    ((uint32_t*)lo)[i * 2]     = pk2(l0, l1);
    ((uint32_t*)lo)[i * 2 + 1] = pk2(l2, l3);
}

// W[k][n] -> Wt[n][k] split into bf16 hi/lo. grid (24,24), block (32,8).
__global__ void wsplit_kernel(const float* __restrict__ W,
                              __nv_bfloat16* __restrict__ hi,
                              __nv_bfloat16* __restrict__ lo)
{
    __shared__ float t[32][33];
    const int x0 = blockIdx.x * 32;
    const int y0 = blockIdx.y * 32;
    const int tx = threadIdx.x, ty = threadIdx.y;
#pragma unroll
    for (int r = 0; r < 4; r++)
        t[ty + r * 8][tx] = W[(size_t)(y0 + ty + r * 8) * ND + x0 + tx];
    __syncthreads();
#pragma unroll
    for (int r = 0; r < 4; r++) {
        float v = t[tx][ty + r * 8];
        __nv_bfloat16 h, l;
        split1(v, h, l);
        size_t o = (size_t)(x0 + ty + r * 8) * ND + y0 + tx;
        hi[o] = h; lo[o] = l;
    }
}

// ---------------- mma.sync GEMM (3-stage pipeline) ----------------
// MODE 0: QKV merged — B=[2304][768]; Q,K -> bf16 hi/lo [b,h,t,hd]; V -> hi/lo [b,h,hd,t].
// MODE 1: Wo — B=[768][768], output fp32 row-major + bias.
#define BK 64
#define KCH (ND / BK)                    // 12
#define TILE_B  16384
#define STAGE_B (4 * TILE_B)             // 64KB
#define GEMM_SMEM (3 * STAGE_B)          // 192KB

__device__ __forceinline__ uint32_t swz(int row, int colbytes) {
    return (uint32_t)(row * 128 + (colbytes ^ ((row & 7) * 16)));
}

template <int MODE>
__global__ __launch_bounds__(256, 1) void gemm_mma(
    const __nv_bfloat16* __restrict__ Ahi, const __nv_bfloat16* __restrict__ Alo,
    const __nv_bfloat16* __restrict__ Bhi, const __nv_bfloat16* __restrict__ Blo,
    float* __restrict__ out, const float* __restrict__ bias,
    __nv_bfloat16* __restrict__ q_hi, __nv_bfloat16* __restrict__ q_lo,
    __nv_bfloat16* __restrict__ k_hi, __nv_bfloat16* __restrict__ k_lo,
    __nv_bfloat16* __restrict__ vt_hi, __nv_bfloat16* __restrict__ vt_lo)
{
    extern __shared__ char smem[];
    const uint32_t sb = (uint32_t)__cvta_generic_to_shared(smem);
    const int tid  = threadIdx.x;
    const int wid  = tid >> 5;
    const int lane = tid & 31;
    const int bx = blockIdx.x, by = blockIdx.y;
    const int wm = wid >> 2;
    const int wn = wid & 3;

    const size_t aRow = (size_t)by * 128;
    const size_t bRow = (size_t)bx * 128;

    const int ldrow = tid >> 3;
    const int ldck  = tid & 7;

    auto load_chunk = [&](int c, int s) {
        const int kb = c * BK;
        const uint32_t base = sb + s * STAGE_B;
#pragma unroll
        for (int q = 0; q < 4; q++) {
            const int row = ldrow + q * 32;
            const uint32_t so = swz(row, ldck * 16);
            const size_t goa = (aRow + row) * ND + kb + ldck * 8;
            const size_t gob = (bRow + row) * ND + kb + ldck * 8;
            CP_ASYNC16(base + 0 * TILE_B + so, Ahi + goa);
            CP_ASYNC16(base + 1 * TILE_B + so, Alo + goa);
            CP_ASYNC16(base + 2 * TILE_B + so, Bhi + gob);
            CP_ASYNC16(base + 3 * TILE_B + so, Blo + gob);
        }
        CP_COMMIT();
    };

    const int a_rofs = ((lane >> 3) & 1) * 8 + (lane & 7);
    const int a_k8   = (lane >> 4) * 8;
    const int b_rofs = (lane >> 4) * 8 + (lane & 7);
    const int b_k8   = ((lane >> 3) & 1) * 8;

    float acc[4][4][4];
#pragma unroll
    for (int mt = 0; mt < 4; mt++)
#pragma unroll
        for (int nt = 0; nt < 4; nt++)
#pragma unroll
            for (int e = 0; e < 4; e++) acc[mt][nt][e] = 0.f;

    load_chunk(0, 0);
    load_chunk(1, 1);

    for (int c = 0; c < KCH; c++) {
        if (c < KCH - 1) { CP_WAIT(1); } else { CP_WAIT(0); }
        __syncthreads();

        const uint32_t base = sb + (c % 3) * STAGE_B;
#pragma unroll
        for (int ks = 0; ks < 4; ks++) {
            uint32_t ah[4][4], al[4][4], bh[4][2], bl[4][2];
#pragma unroll
            for (int mt = 0; mt < 4; mt++) {
                const int row = wm * 64 + mt * 16 + a_rofs;
                const uint32_t so = swz(row, (ks * 16 + a_k8) * 2);
                ldsm4(ah[mt][0], ah[mt][1], ah[mt][2], ah[mt][3],
                      base + 0 * TILE_B + so);
                ldsm4(al[mt][0], al[mt][1], al[mt][2], al[mt][3],
                      base + 1 * TILE_B + so);
            }
#pragma unroll
            for (int p = 0; p < 2; p++) {
                const int row = wn * 32 + p * 16 + b_rofs;
                const uint32_t so = swz(row, (ks * 16 + b_k8) * 2);
                ldsm4(bh[2 * p][0], bh[2 * p][1], bh[2 * p + 1][0], bh[2 * p + 1][1],
                      base + 2 * TILE_B + so);
                ldsm4(bl[2 * p][0], bl[2 * p][1], bl[2 * p + 1][0], bl[2 * p + 1][1],
                      base + 3 * TILE_B + so);
            }
#pragma unroll
            for (int mt = 0; mt < 4; mt++)
#pragma unroll
                for (int nt = 0; nt < 4; nt++) {
                    mma16816(acc[mt][nt], ah[mt], bh[nt]);
                    mma16816(acc[mt][nt], ah[mt], bl[nt]);
                    mma16816(acc[mt][nt], al[mt], bh[nt]);
                }
        }
        if (c + 2 < KCH) load_chunk(c + 2, (c + 2) % 3);
    }

    // Epilogue
    const int g = lane >> 2, t = lane & 3;
#pragma unroll
    for (int mt = 0; mt < 4; mt++) {
#pragma unroll
        for (int nt = 0; nt < 4; nt++) {
            const int col = wn * 32 + nt * 8 + t * 2;
#pragma unroll
            for (int half = 0; half < 2; half++) {
                const int row = wm * 64 + mt * 16 + g + half * 8;
                float2 v = make_float2(acc[mt][nt][half * 2],
                                       acc[mt][nt][half * 2 + 1]);
                if (MODE == 0) {
                    const int tensor = bx / 6;
                    const int wc = (bx % 6) * 128 + col;
                    const int h = wc >> 6, d = wc & 63;
                    __nv_bfloat16 h0, l0, h1, l1;
                    split1(v.x, h0, l0);
                    split1(v.y, h1, l1);
                    if (tensor < 2) {
                        __nv_bfloat16* dh = tensor ? k_hi : q_hi;
                        __nv_bfloat16* dl = tensor ? k_lo : q_lo;
                        const size_t o = (((size_t)(by * NH + h) * NT + row) * NHD + d) >> 1;
                        ((uint32_t*)dh)[o] = pk2(h0, h1);
                        ((uint32_t*)dl)[o] = pk2(l0, l1);
                    } else {
                        const size_t o = ((size_t)(by * NH + h) * NHD + d) * NT + row;
                        vt_hi[o] = h0;      vt_lo[o] = l0;
                        vt_hi[o + NT] = h1; vt_lo[o + NT] = l1;
                    }
                } else {
                    const int gcol = bx * 128 + col;
                    v.x += bias[gcol]; v.y += bias[gcol + 1];
                    *(float2*)(out + (size_t)(by * 128 + row) * ND + gcol) = v;
                }
            }
        }
    }
}

// ---------------- tensor-core attention ----------------
// One CTA per (b,h). T=128, hd=64. 8 warps (2x4). Inputs pre-split bf16 hi/lo.
// Smem (byte offsets):
//   QHI 0, QLO 18432, KHI 36864, KLO 55296      (128 rows x 72 bf16, stride 144B)
//   PHI 0, PLO 36864  (union over Q/K after S)  (128 rows x 136 bf16, stride 272B)
//   VTHI 73728, VTLO 91136                      (64 rows x 136 bf16, stride 272B)
//   S 108544 (fp32, 128 rows x 136, stride 544B)
#define AQ_HI 0
#define AQ_LO 18432
#define AK_HI 36864
#define AK_LO 55296
#define AP_HI 0
#define AP_LO 36864
#define AV_HI 73728
#define AV_LO 91136
#define AS_F  108544
#define ATTN_SMEM 178176

__global__ __launch_bounds__(256, 1) void attn_tc(
    const __nv_bfloat16* __restrict__ q_hi, const __nv_bfloat16* __restrict__ q_lo,
    const __nv_bfloat16* __restrict__ k_hi, const __nv_bfloat16* __restrict__ k_lo,
    const __nv_bfloat16* __restrict__ vt_hi, const __nv_bfloat16* __restrict__ vt_lo,
    __nv_bfloat16* __restrict__ chi, __nv_bfloat16* __restrict__ clo)
{
    extern __shared__ char sm[];
    const uint32_t sb = (uint32_t)__cvta_generic_to_shared(sm);
    const int tid  = threadIdx.x;
    const int wid  = tid >> 5;
    const int lane = tid & 31;
    const int bh = blockIdx.x;
    const int b  = bh / NH;
    const int h  = bh - b * NH;
    const int wm = wid >> 2;       // 0..1
    const int wn = wid & 3;        // 0..3

    const size_t base = (size_t)bh * (NT * NHD);
    float* S = (float*)(sm + AS_F);

    // ---- direct cp.async loads of pre-split operands ----
    for (int idx = tid; idx < 1024; idx += 256) {        // Q/K: 128 rows x 8 chunks
        const int row = idx >> 3, ck = idx & 7;
        const size_t go = base + row * NHD + ck * 8;
        const uint32_t so = row * 144 + ck * 16;
        CP_ASYNC16(sb + AQ_HI + so, q_hi + go);
        CP_ASYNC16(sb + AQ_LO + so, q_lo + go);
        CP_ASYNC16(sb + AK_HI + so, k_hi + go);
        CP_ASYNC16(sb + AK_LO + so, k_lo + go);
    }
    for (int idx = tid; idx < 1024; idx += 256) {        // VT: 64 rows x 16 chunks
        const int row = idx >> 4, ck = idx & 15;
        const size_t go = base + row * NT + ck * 8;
        const uint32_t so = row * 272 + ck * 16;
        CP_ASYNC16(sb + AV_HI + so, vt_hi + go);
        CP_ASYNC16(sb + AV_LO + so, vt_lo + go);
    }
    CP_COMMIT();
    CP_WAIT(0);
    __syncthreads();

    const int a_rofs = ((lane >> 3) & 1) * 8 + (lane & 7);
    const int a_k8   = (lane >> 4) * 8;
    const int b_rofs = (lane >> 4) * 8 + (lane & 7);
    const int b_k8   = ((lane >> 3) & 1) * 8;
    const int g = lane >> 2, t = lane & 3;

    // ---- S = Q K^T (M=128,N=128,K=64), skip fully-masked tiles ----
    const bool skip = (wm == 0 && wn >= 2);
    if (!skip) {
        float acc[4][4][4];
#pragma unroll
        for (int mt = 0; mt < 4; mt++)
#pragma unroll
            for (int nt = 0; nt < 4; nt++)
#pragma unroll
                for (int e = 0; e < 4; e++) acc[mt][nt][e] = 0.f;

#pragma unroll
        for (int ks = 0; ks < 4; ks++) {
            uint32_t ah[4][4], al[4][4], bh[4][2], bl[4][2];
#pragma unroll
            for (int mt = 0; mt < 4; mt++) {
                const int row = wm * 64 + mt * 16 + a_rofs;
                const uint32_t off = row * 144 + (ks * 16 + a_k8) * 2;
                ldsm4(ah[mt][0], ah[mt][1], ah[mt][2], ah[mt][3], sb + AQ_HI + off);
                ldsm4(al[mt][0], al[mt][1], al[mt][2], al[mt][3], sb + AQ_LO + off);
            }
#pragma unroll
            for (int p = 0; p < 2; p++) {
                const int row = wn * 32 + p * 16 + b_rofs;
                const uint32_t off = row * 144 + (ks * 16 + b_k8) * 2;
                ldsm4(bh[2 * p][0], bh[2 * p][1], bh[2 * p + 1][0], bh[2 * p + 1][1],
                      sb + AK_HI + off);
                ldsm4(bl[2 * p][0], bl[2 * p][1], bl[2 * p + 1][0], bl[2 * p + 1][1],
                      sb + AK_LO + off);
            }
#pragma unroll
            for (int mt = 0; mt < 4; mt++)
#pragma unroll
                for (int nt = 0; nt < 4; nt++) {
                    mma16816(acc[mt][nt], ah[mt], bh[nt]);
                    mma16816(acc[mt][nt], ah[mt], bl[nt]);
                    mma16816(acc[mt][nt], al[mt], bh[nt]);
                }
        }
#pragma unroll
        for (int mt = 0; mt < 4; mt++)
#pragma unroll
            for (int nt = 0; nt < 4; nt++) {
                const int col = wn * 32 + nt * 8 + t * 2;
#pragma unroll
                for (int half = 0; half < 2; half++) {
                    const int row = wm * 64 + mt * 16 + g + half * 8;
                    *(float2*)(S + row * 136 + col) =
                        make_float2(acc[mt][nt][half * 2], acc[mt][nt][half * 2 + 1]);
                }
            }
    }
    __syncthreads();

    // ---- causal softmax: warp per 16 rows, lane covers 4 cols ----
    {
        const float scale = 0.125f;  // 1/sqrt(64)
#pragma unroll
        for (int rr = 0; rr < 16; rr++) {
            const int r = wid * 16 + rr;
            float4 sv = *(const float4*)(S + r * 136 + lane * 4);
            const int j0 = lane * 4;
            float s0 = (j0 + 0 <= r) ? sv.x : -INFINITY;
            float s1 = (j0 + 1 <= r) ? sv.y : -INFINITY;
            float s2 = (j0 + 2 <= r) ? sv.z : -INFINITY;
            float s3 = (j0 + 3 <= r) ? sv.w : -INFINITY;
            float m = fmaxf(fmaxf(s0, s1), fmaxf(s2, s3));
#pragma unroll
            for (int o = 16; o; o >>= 1)
                m = fmaxf(m, __shfl_xor_sync(0xFFFFFFFFu, m, o));
            float e0 = __expf((s0 - m) * scale);
            float e1 = __expf((s1 - m) * scale);
            float e2 = __expf((s2 - m) * scale);
            float e3 = __expf((s3 - m) * scale);
            float sum = (e0 + e1) + (e2 + e3);
#pragma unroll
            for (int o = 16; o; o >>= 1)
                sum += __shfl_xor_sync(0xFFFFFFFFu, sum, o);
            const float inv = 1.f / sum;
            __nv_bfloat16 h0, l0, h1, l1, h2, l2, h3, l3;
            split1(e0 * inv, h0, l0);
            split1(e1 * inv, h1, l1);
            split1(e2 * inv, h2, l2);
            split1(e3 * inv, h3, l3);
            *(uint2*)(sm + AP_HI + r * 272 + lane * 8) =
                make_uint2(pk2(h0, h1), pk2(h2, h3));
            *(uint2*)(sm + AP_LO + r * 272 + lane * 8) =
                make_uint2(pk2(l0, l1), pk2(l2, l3));
        }
    }
    __syncthreads();

    // ---- ctx = P V (M=128,N=64,K=128), warp tile 64x16; write bf16 hi/lo ----
    {
        float acc[4][2][4];
#pragma unroll
        for (int mt = 0; mt < 4; mt++)
#pragma unroll
            for (int nt = 0; nt < 2; nt++)
#pragma unroll
                for (int e = 0; e < 4; e++) acc[mt][nt][e] = 0.f;

#pragma unroll
        for (int ks = 0; ks < 8; ks++) {
            uint32_t ph[4][4], pl[4][4], vh[2][2], vl[2][2];
#pragma unroll
            for (int mt = 0; mt < 4; mt++) {
                const int row = wm * 64 + mt * 16 + a_rofs;
                const uint32_t off = row * 272 + (ks * 16 + a_k8) * 2;
                ldsm4(ph[mt][0], ph[mt][1], ph[mt][2], ph[mt][3], sb + AP_HI + off);
                ldsm4(pl[mt][0], pl[mt][1], pl[mt][2], pl[mt][3], sb + AP_LO + off);
            }
            {
                const int row = wn * 16 + b_rofs;
                const uint32_t off = row * 272 + (ks * 16 + b_k8) * 2;
                ldsm4(vh[0][0], vh[0][1], vh[1][0], vh[1][1], sb + AV_HI + off);
                ldsm4(vl[0][0], vl[0][1], vl[1][0], vl[1][1], sb + AV_LO + off);
            }
#pragma unroll
            for (int mt = 0; mt < 4; mt++)
#pragma unroll
                for (int nt = 0; nt < 2; nt++) {
                    mma16816(acc[mt][nt], ph[mt], vh[nt]);
                    mma16816(acc[mt][nt], ph[mt], vl[nt]);
                    mma16816(acc[mt][nt], pl[mt], vh[nt]);
                }
        }
#pragma unroll
        for (int mt = 0; mt < 4; mt++)
#pragma unroll
            for (int nt = 0; nt < 2; nt++) {
                const int col = wn * 16 + nt * 8 + t * 2;
#pragma unroll
                for (int half = 0; half < 2; half++) {
                    const int row = wm * 64 + mt * 16 + g + half * 8;
                    __nv_bfloat16 h0, l0, h1, l1;
                    split1(acc[mt][nt][half * 2], h0, l0);
                    split1(acc[mt][nt][half * 2 + 1], h1, l1);
                    const size_t o = (((size_t)(b * NT + row)) * ND + h * NHD + col) >> 1;
                    ((uint32_t*)chi)[o] = pk2(h0, h1);
                    ((uint32_t*)clo)[o] = pk2(l0, l1);
                }
            }
    }
}

// ---------------- launch ----------------
extern "C" void kernel_launch(void* const* d_in, const int* in_sizes, int n_in,
                              void* d_out, int out_size)
{
    const float* x  = (const float*)d_in[0];
    const float* Wq = (const float*)d_in[1];
    const float* Wk = (const float*)d_in[2];
    const float* Wv = (const float*)d_in[3];
    const float* Wo = (const float*)d_in[4];
    const float* bo = (const float*)d_in[5];
    float* out = (float*)d_out;

    void *pqh, *pql, *pkh, *pkl, *pvh, *pvl, *pahi, *palo, *pwthi, *pwtlo;
    cudaGetSymbolAddress(&pqh, g_qhi);  cudaGetSymbolAddress(&pql, g_qlo);
    cudaGetSymbolAddress(&pkh, g_khi);  cudaGetSymbolAddress(&pkl, g_klo);
    cudaGetSymbolAddress(&pvh, g_vthi); cudaGetSymbolAddress(&pvl, g_vtlo);
    cudaGetSymbolAddress(&pahi, g_ahi); cudaGetSymbolAddress(&palo, g_alo);
    cudaGetSymbolAddress(&pwthi, g_wthi);
    cudaGetSymbolAddress(&pwtlo, g_wtlo);
    __nv_bfloat16* ahi  = (__nv_bfloat16*)pahi;
    __nv_bfloat16* alo  = (__nv_bfloat16*)palo;
    __nv_bfloat16* wthi = (__nv_bfloat16*)pwthi;
    __nv_bfloat16* wtlo = (__nv_bfloat16*)pwtlo;

    cudaFuncSetAttribute(gemm_mma<0>,
                         cudaFuncAttributeMaxDynamicSharedMemorySize, GEMM_SMEM);
    cudaFuncSetAttribute(gemm_mma<1>,
                         cudaFuncAttributeMaxDynamicSharedMemorySize, GEMM_SMEM);
    cudaFuncSetAttribute(attn_tc,
                         cudaFuncAttributeMaxDynamicSharedMemorySize, ATTN_SMEM);

    const int n4 = BT * ND / 4;
    dim3 wgrid(ND / 32, ND / 32);
    dim3 wblk(32, 8);

    // 1) split x -> bf16 hi/lo
    split4_kernel<<<(n4 + 255) / 256, 256>>>(x, ahi, alo, n4);
    // 2) transpose+split all weights (qkv slots contiguous -> [2304][768])
    wsplit_kernel<<<wgrid, wblk>>>(Wq, wthi + 0 * ND * ND, wtlo + 0 * ND * ND);
    wsplit_kernel<<<wgrid, wblk>>>(Wk, wthi + 1 * ND * ND, wtlo + 1 * ND * ND);
    wsplit_kernel<<<wgrid, wblk>>>(Wv, wthi + 2 * ND * ND, wtlo + 2 * ND * ND);
    wsplit_kernel<<<wgrid, wblk>>>(Wo, wthi + 3 * ND * ND, wtlo + 3 * ND * ND);
    // 3) merged QKV projection -> pre-split Q/K [b,h,t,hd] + V^T [b,h,hd,t]
    {
        dim3 ggrid(18, BT / 128);
        gemm_mma<0><<<ggrid, 256, GEMM_SMEM>>>(ahi, alo, wthi, wtlo,
            nullptr, nullptr,
            (__nv_bfloat16*)pqh, (__nv_bfloat16*)pql,
            (__nv_bfloat16*)pkh, (__nv_bfloat16*)pkl,
            (__nv_bfloat16*)pvh, (__nv_bfloat16*)pvl);
    }
    // 4) tensor-core attention, writes ctx pre-split into ahi/alo
    attn_tc<<<NB * NH, 256, ATTN_SMEM>>>(
        (const __nv_bfloat16*)pqh, (const __nv_bfloat16*)pql,
        (const __nv_bfloat16*)pkh, (const __nv_bfloat16*)pkl,
        (const __nv_bfloat16*)pvh, (const __nv_bfloat16*)pvl,
        ahi, alo);
    // 5) output projection with bias
    {
        dim3 ggrid(6, BT / 128);
        gemm_mma<1><<<ggrid, 256, GEMM_SMEM>>>(ahi, alo,
            wthi + 3 * ND * ND, wtlo + 3 * ND * ND, out, bo,
            nullptr, nullptr, nullptr, nullptr, nullptr, nullptr);
    }
}

// round 10
// speedup vs baseline: 8.9228x; 2.3179x over previous
#include <cuda_runtime.h>
#include <cuda_fp16.h>
#include <cstdint>

// Problem: x[512,128,768] fp32; Wq/k/v/o [768,768]; bo[768]; out[512,128,768] fp32.
#define NB   512
#define NT   128
#define ND   768
#define NH   12
#define NHD  64
#define BT   (NB * NT)          // 65536
#define HSZ  (NB * NH * NT * NHD)

// ---------------- scratch ----------------
__device__ __align__(256) __half g_q16[HSZ];          // [b,h,t,hd]
__device__ __align__(256) __half g_k16[HSZ];          // [b,h,t,hd]
__device__ __align__(256) __half g_vt16[HSZ];         // [b,h,hd,t]
__device__ __align__(256) __half g_a16[BT * ND];      // x-fp16, then ctx-fp16
__device__ __align__(256) __half g_wt16[4 * ND * ND]; // W^T fp16 (q,k,v,o)

// ---------------- PTX helpers ----------------
#define CP_ASYNC16(smem, gmem) \
    asm volatile("cp.async.cg.shared.global [%0], [%1], 16;" :: "r"(smem), "l"(gmem))
#define CP_COMMIT()  asm volatile("cp.async.commit_group;" ::: "memory")
#define CP_WAIT(n)   asm volatile("cp.async.wait_group %0;" :: "n"(n) : "memory")

__device__ __forceinline__ void ldsm4(uint32_t& r0, uint32_t& r1, uint32_t& r2,
                                      uint32_t& r3, uint32_t addr) {
    asm volatile("ldmatrix.sync.aligned.m8n8.x4.shared.b16 {%0,%1,%2,%3}, [%4];"
                 : "=r"(r0), "=r"(r1), "=r"(r2), "=r"(r3) : "r"(addr));
}
__device__ __forceinline__ void mma16816(float* c, const uint32_t* a,
                                         const uint32_t* b) {
    asm volatile(
        "mma.sync.aligned.m16n8k16.row.col.f32.f16.f16.f32 "
        "{%0,%1,%2,%3}, {%4,%5,%6,%7}, {%8,%9}, {%0,%1,%2,%3};"
        : "+f"(c[0]), "+f"(c[1]), "+f"(c[2]), "+f"(c[3])
        : "r"(a[0]), "r"(a[1]), "r"(a[2]), "r"(a[3]), "r"(b[0]), "r"(b[1]));
}

// ---------------- conversion kernels ----------------
__global__ __launch_bounds__(256) void cvt4_kernel(
    const float* __restrict__ in, __half* __restrict__ out, int n4)
{
    int i = blockIdx.x * 256 + threadIdx.x;
    if (i >= n4) return;
    float4 v = ((const float4*)in)[i];
    __half2* o = (__half2*)out;
    o[i * 2]     = __floats2half2_rn(v.x, v.y);
    o[i * 2 + 1] = __floats2half2_rn(v.z, v.w);
}

// W[k][n] -> Wt[n][k] fp16. grid (24,24), block (32,8).
__global__ void wcvt_kernel(const float* __restrict__ W, __half* __restrict__ o)
{
    __shared__ float t[32][33];
    const int x0 = blockIdx.x * 32;
    const int y0 = blockIdx.y * 32;
    const int tx = threadIdx.x, ty = threadIdx.y;
#pragma unroll
    for (int r = 0; r < 4; r++)
        t[ty + r * 8][tx] = W[(size_t)(y0 + ty + r * 8) * ND + x0 + tx];
    __syncthreads();
#pragma unroll
    for (int r = 0; r < 4; r++)
        o[(size_t)(x0 + ty + r * 8) * ND + y0 + tx] = __float2half(t[tx][ty + r * 8]);
}

// ---------------- mma.sync GEMM (3-stage, 2 CTA/SM) ----------------
// MODE 0: QKV merged — B=[2304][768]; Q,K -> fp16 [b,h,t,hd]; V -> fp16 [b,h,hd,t].
// MODE 1: Wo — B=[768][768], output fp32 row-major + bias.
#define BK 64
#define KCH (ND / BK)                    // 12
#define TILE_B  16384                    // 128 rows x 128B
#define STAGE_B (2 * TILE_B)             // 32KB (A + B)
#define GEMM_SMEM (3 * STAGE_B)          // 96KB

__device__ __forceinline__ uint32_t swz(int row, int colbytes) {
    return (uint32_t)(row * 128 + (colbytes ^ ((row & 7) * 16)));
}

template <int MODE>
__global__ __launch_bounds__(256, 2) void gemm_mma(
    const __half* __restrict__ A, const __half* __restrict__ B,
    float* __restrict__ out, const float* __restrict__ bias,
    __half* __restrict__ q16, __half* __restrict__ k16, __half* __restrict__ vt16)
{
    extern __shared__ char smem[];
    const uint32_t sb = (uint32_t)__cvta_generic_to_shared(smem);
    const int tid  = threadIdx.x;
    const int wid  = tid >> 5;
    const int lane = tid & 31;
    const int bx = blockIdx.x, by = blockIdx.y;
    const int wm = wid >> 2;
    const int wn = wid & 3;

    const size_t aRow = (size_t)by * 128;
    const size_t bRow = (size_t)bx * 128;

    const int ldrow = tid >> 3;
    const int ldck  = tid & 7;

    auto load_chunk = [&](int c, int s) {
        const int kb = c * BK;
        const uint32_t base = sb + s * STAGE_B;
#pragma unroll
        for (int q = 0; q < 4; q++) {
            const int row = ldrow + q * 32;
            const uint32_t so = swz(row, ldck * 16);
            CP_ASYNC16(base + so,          A + (aRow + row) * ND + kb + ldck * 8);
            CP_ASYNC16(base + TILE_B + so, B + (bRow + row) * ND + kb + ldck * 8);
        }
        CP_COMMIT();
    };

    const int a_rofs = ((lane >> 3) & 1) * 8 + (lane & 7);
    const int a_k8   = (lane >> 4) * 8;
    const int b_rofs = (lane >> 4) * 8 + (lane & 7);
    const int b_k8   = ((lane >> 3) & 1) * 8;

    float acc[4][4][4];
#pragma unroll
    for (int mt = 0; mt < 4; mt++)
#pragma unroll
        for (int nt = 0; nt < 4; nt++)
#pragma unroll
            for (int e = 0; e < 4; e++) acc[mt][nt][e] = 0.f;

    load_chunk(0, 0);
    load_chunk(1, 1);

    for (int c = 0; c < KCH; c++) {
        if (c < KCH - 1) { CP_WAIT(1); } else { CP_WAIT(0); }
        __syncthreads();

        const uint32_t base = sb + (c % 3) * STAGE_B;
#pragma unroll
        for (int ks = 0; ks < 4; ks++) {
            uint32_t af[4][4], bf[4][2];
#pragma unroll
            for (int mt = 0; mt < 4; mt++) {
                const int row = wm * 64 + mt * 16 + a_rofs;
                ldsm4(af[mt][0], af[mt][1], af[mt][2], af[mt][3],
                      base + swz(row, (ks * 16 + a_k8) * 2));
            }
#pragma unroll
            for (int p = 0; p < 2; p++) {
                const int row = wn * 32 + p * 16 + b_rofs;
                ldsm4(bf[2 * p][0], bf[2 * p][1], bf[2 * p + 1][0], bf[2 * p + 1][1],
                      base + TILE_B + swz(row, (ks * 16 + b_k8) * 2));
            }
#pragma unroll
            for (int mt = 0; mt < 4; mt++)
#pragma unroll
                for (int nt = 0; nt < 4; nt++)
                    mma16816(acc[mt][nt], af[mt], bf[nt]);
        }
        if (c + 2 < KCH) load_chunk(c + 2, (c + 2) % 3);
    }

    // Epilogue
    const int g = lane >> 2, t = lane & 3;
#pragma unroll
    for (int mt = 0; mt < 4; mt++) {
#pragma unroll
        for (int nt = 0; nt < 4; nt++) {
            const int col = wn * 32 + nt * 8 + t * 2;
#pragma unroll
            for (int half = 0; half < 2; half++) {
                const int row = wm * 64 + mt * 16 + g + half * 8;
                float2 v = make_float2(acc[mt][nt][half * 2],
                                       acc[mt][nt][half * 2 + 1]);
                if (MODE == 0) {
                    const int tensor = bx / 6;
                    const int wc = (bx % 6) * 128 + col;
                    const int h = wc >> 6, d = wc & 63;
                    if (tensor < 2) {
                        __half* dst = tensor ? k16 : q16;
                        const size_t o = ((size_t)(by * NH + h) * NT + row) * NHD + d;
                        ((__half2*)dst)[o >> 1] = __floats2half2_rn(v.x, v.y);
                    } else {
                        const size_t o = ((size_t)(by * NH + h) * NHD + d) * NT + row;
                        vt16[o]      = __float2half(v.x);
                        vt16[o + NT] = __float2half(v.y);
                    }
                } else {
                    const int gcol = bx * 128 + col;
                    v.x += bias[gcol]; v.y += bias[gcol + 1];
                    *(float2*)(out + (size_t)(by * 128 + row) * ND + gcol) = v;
                }
            }
        }
    }
}

// ---------------- tensor-core attention (fp16 single) ----------------
// One CTA per (b,h). 8 warps (2x4).
// Smem: Q 0 (128x144B), K 18432 (128x144B), P 0 (union, 128x272B=34816<=36864),
//       VT 36864 (64x272B), S 54272 (fp32 128 x 136 floats, 544B stride).
#define AQ_S 0
#define AK_S 18432
#define AP_S 0
#define AV_S 36864
#define AS_F 54272
#define ATTN_SMEM 123904

__global__ __launch_bounds__(256, 1) void attn_tc(
    const __half* __restrict__ q16, const __half* __restrict__ k16,
    const __half* __restrict__ vt16, __half* __restrict__ c16)
{
    extern __shared__ char sm[];
    const uint32_t sb = (uint32_t)__cvta_generic_to_shared(sm);
    const int tid  = threadIdx.x;
    const int wid  = tid >> 5;
    const int lane = tid & 31;
    const int bh = blockIdx.x;
    const int b  = bh / NH;
    const int h  = bh - b * NH;
    const int wm = wid >> 2;       // 0..1
    const int wn = wid & 3;        // 0..3

    const size_t base = (size_t)bh * (NT * NHD);
    float* S = (float*)(sm + AS_F);

    // ---- cp.async loads ----
    for (int idx = tid; idx < 1024; idx += 256) {        // Q/K: 128 rows x 8 chunks
        const int row = idx >> 3, ck = idx & 7;
        const size_t go = base + row * NHD + ck * 8;
        const uint32_t so = row * 144 + ck * 16;
        CP_ASYNC16(sb + AQ_S + so, q16 + go);
        CP_ASYNC16(sb + AK_S + so, k16 + go);
    }
    for (int idx = tid; idx < 1024; idx += 256) {        // VT: 64 rows x 16 chunks
        const int row = idx >> 4, ck = idx & 15;
        const size_t go = base + row * NT + ck * 8;
        CP_ASYNC16(sb + AV_S + row * 272 + ck * 16, vt16 + go);
    }
    CP_COMMIT();
    CP_WAIT(0);
    __syncthreads();

    const int a_rofs = ((lane >> 3) & 1) * 8 + (lane & 7);
    const int a_k8   = (lane >> 4) * 8;
    const int b_rofs = (lane >> 4) * 8 + (lane & 7);
    const int b_k8   = ((lane >> 3) & 1) * 8;
    const int g = lane >> 2, t = lane & 3;

    // ---- S = Q K^T (M=128,N=128,K=64), skip fully-masked warp tiles ----
    if (!(wm == 0 && wn >= 2)) {
        float acc[4][4][4];
#pragma unroll
        for (int mt = 0; mt < 4; mt++)
#pragma unroll
            for (int nt = 0; nt < 4; nt++)
#pragma unroll
                for (int e = 0; e < 4; e++) acc[mt][nt][e] = 0.f;

#pragma unroll
        for (int ks = 0; ks < 4; ks++) {
            uint32_t af[4][4], bf[4][2];
#pragma unroll
            for (int mt = 0; mt < 4; mt++) {
                const int row = wm * 64 + mt * 16 + a_rofs;
                ldsm4(af[mt][0], af[mt][1], af[mt][2], af[mt][3],
                      sb + AQ_S + row * 144 + (ks * 16 + a_k8) * 2);
            }
#pragma unroll
            for (int p = 0; p < 2; p++) {
                const int row = wn * 32 + p * 16 + b_rofs;
                ldsm4(bf[2 * p][0], bf[2 * p][1], bf[2 * p + 1][0], bf[2 * p + 1][1],
                      sb + AK_S + row * 144 + (ks * 16 + b_k8) * 2);
            }
#pragma unroll
            for (int mt = 0; mt < 4; mt++)
#pragma unroll
                for (int nt = 0; nt < 4; nt++)
                    mma16816(acc[mt][nt], af[mt], bf[nt]);
        }
#pragma unroll
        for (int mt = 0; mt < 4; mt++)
#pragma unroll
            for (int nt = 0; nt < 4; nt++) {
                const int col = wn * 32 + nt * 8 + t * 2;
#pragma unroll
                for (int half = 0; half < 2; half++) {
                    const int row = wm * 64 + mt * 16 + g + half * 8;
                    *(float2*)(S + row * 136 + col) =
                        make_float2(acc[mt][nt][half * 2], acc[mt][nt][half * 2 + 1]);
                }
            }
    }
    __syncthreads();

    // ---- causal softmax: warp per 16 rows; write P fp16 ----
    {
        const float scale = 0.125f;
#pragma unroll
        for (int rr = 0; rr < 16; rr++) {
            const int r = wid * 16 + rr;
            float4 sv = *(const float4*)(S + r * 136 + lane * 4);
            const int j0 = lane * 4;
            float s0 = (j0 + 0 <= r) ? sv.x : -INFINITY;
            float s1 = (j0 + 1 <= r) ? sv.y : -INFINITY;
            float s2 = (j0 + 2 <= r) ? sv.z : -INFINITY;
            float s3 = (j0 + 3 <= r) ? sv.w : -INFINITY;
            float m = fmaxf(fmaxf(s0, s1), fmaxf(s2, s3));
#pragma unroll
            for (int o = 16; o; o >>= 1)
                m = fmaxf(m, __shfl_xor_sync(0xFFFFFFFFu, m, o));
            float e0 = __expf((s0 - m) * scale);
            float e1 = __expf((s1 - m) * scale);
            float e2 = __expf((s2 - m) * scale);
            float e3 = __expf((s3 - m) * scale);
            float sum = (e0 + e1) + (e2 + e3);
#pragma unroll
            for (int o = 16; o; o >>= 1)
                sum += __shfl_xor_sync(0xFFFFFFFFu, sum, o);
            const float inv = 1.f / sum;
            __half2 p01 = __floats2half2_rn(e0 * inv, e1 * inv);
            __half2 p23 = __floats2half2_rn(e2 * inv, e3 * inv);
            *(uint2*)(sm + AP_S + r * 272 + lane * 8) =
                make_uint2(*(uint32_t*)&p01, *(uint32_t*)&p23);
        }
    }
    __syncthreads();

    // ---- ctx = P V (M=128,N=64,K=128), warp tile 64x16; write fp16 ----
    {
        float acc[4][2][4];
#pragma unroll
        for (int mt = 0; mt < 4; mt++)
#pragma unroll
            for (int nt = 0; nt < 2; nt++)
#pragma unroll
                for (int e = 0; e < 4; e++) acc[mt][nt][e] = 0.f;

#pragma unroll
        for (int ks = 0; ks < 8; ks++) {
            uint32_t pf[4][4], vf[2][2];
#pragma unroll
            for (int mt = 0; mt < 4; mt++) {
                const int row = wm * 64 + mt * 16 + a_rofs;
                ldsm4(pf[mt][0], pf[mt][1], pf[mt][2], pf[mt][3],
                      sb + AP_S + row * 272 + (ks * 16 + a_k8) * 2);
            }
            {
                const int row = wn * 16 + b_rofs;
                ldsm4(vf[0][0], vf[0][1], vf[1][0], vf[1][1],
                      sb + AV_S + row * 272 + (ks * 16 + b_k8) * 2);
            }
#pragma unroll
            for (int mt = 0; mt < 4; mt++)
#pragma unroll
                for (int nt = 0; nt < 2; nt++)
                    mma16816(acc[mt][nt], pf[mt], vf[nt]);
        }
#pragma unroll
        for (int mt = 0; mt < 4; mt++)
#pragma unroll
            for (int nt = 0; nt < 2; nt++) {
                const int col = wn * 16 + nt * 8 + t * 2;
#pragma unroll
                for (int half = 0; half < 2; half++) {
                    const int row = wm * 64 + mt * 16 + g + half * 8;
                    const size_t o = ((size_t)(b * NT + row)) * ND + h * NHD + col;
                    ((__half2*)c16)[o >> 1] =
                        __floats2half2_rn(acc[mt][nt][half * 2], acc[mt][nt][half * 2 + 1]);
                }
            }
    }
}

// ---------------- launch ----------------
extern "C" void kernel_launch(void* const* d_in, const int* in_sizes, int n_in,
                              void* d_out, int out_size)
{
    const float* x  = (const float*)d_in[0];
    const float* Wq = (const float*)d_in[1];
    const float* Wk = (const float*)d_in[2];
    const float* Wv = (const float*)d_in[3];
    const float* Wo = (const float*)d_in[4];
    const float* bo = (const float*)d_in[5];
    float* out = (float*)d_out;

    void *pq, *pk, *pv, *pa, *pw;
    cudaGetSymbolAddress(&pq, g_q16);
    cudaGetSymbolAddress(&pk, g_k16);
    cudaGetSymbolAddress(&pv, g_vt16);
    cudaGetSymbolAddress(&pa, g_a16);
    cudaGetSymbolAddress(&pw, g_wt16);
    __half* a16  = (__half*)pa;
    __half* wt16 = (__half*)pw;

    cudaFuncSetAttribute(gemm_mma<0>,
                         cudaFuncAttributeMaxDynamicSharedMemorySize, GEMM_SMEM);
    cudaFuncSetAttribute(gemm_mma<1>,
                         cudaFuncAttributeMaxDynamicSharedMemorySize, GEMM_SMEM);
    cudaFuncSetAttribute(attn_tc,
                         cudaFuncAttributeMaxDynamicSharedMemorySize, ATTN_SMEM);

    const int n4 = BT * ND / 4;
    dim3 wgrid(ND / 32, ND / 32);
    dim3 wblk(32, 8);

    // 1) x -> fp16
    cvt4_kernel<<<(n4 + 255) / 256, 256>>>(x, a16, n4);
    // 2) W^T -> fp16 (qkv slots contiguous -> [2304][768])
    wcvt_kernel<<<wgrid, wblk>>>(Wq, wt16 + 0 * ND * ND);
    wcvt_kernel<<<wgrid, wblk>>>(Wk, wt16 + 1 * ND * ND);
    wcvt_kernel<<<wgrid, wblk>>>(Wv, wt16 + 2 * ND * ND);
    wcvt_kernel<<<wgrid, wblk>>>(Wo, wt16 + 3 * ND * ND);
    // 3) merged QKV projection
    {
        dim3 ggrid(18, BT / 128);
        gemm_mma<0><<<ggrid, 256, GEMM_SMEM>>>(a16, wt16, nullptr, nullptr,
            (__half*)pq, (__half*)pk, (__half*)pv);
    }
    // 4) attention (ctx -> a16, overwriting x which is no longer needed)
    attn_tc<<<NB * NH, 256, ATTN_SMEM>>>((const __half*)pq, (const __half*)pk,
                                         (const __half*)pv, a16);
    // 5) output projection with bias
    {
        dim3 ggrid(6, BT / 128);
        gemm_mma<1><<<ggrid, 256, GEMM_SMEM>>>(a16, wt16 + 3 * ND * ND,
            out, bo, nullptr, nullptr, nullptr);
    }
}

// round 11
// speedup vs baseline: 10.9747x; 1.2300x over previous
#include <cuda_runtime.h>
#include <cuda_fp16.h>
#include <cstdint>

// Problem: x[512,128,768] fp32; Wq/k/v/o [768,768]; bo[768]; out[512,128,768] fp32.
#define NB   512
#define NT   128
#define ND   768
#define NH   12
#define NHD  64
#define BT   (NB * NT)          // 65536
#define HSZ  (NB * NH * NT * NHD)

// ---------------- scratch ----------------
__device__ __align__(256) __half g_q16[HSZ];          // [b,h,t,hd]
__device__ __align__(256) __half g_k16[HSZ];          // [b,h,t,hd]
__device__ __align__(256) __half g_vt16[HSZ];         // [b,h,hd,t]
__device__ __align__(256) __half g_a16[BT * ND];      // x-fp16, then ctx-fp16
__device__ __align__(256) __half g_wt16[4 * ND * ND]; // W^T fp16 (q,k,v,o)

// ---------------- PTX helpers ----------------
#define CP_ASYNC16(smem, gmem) \
    asm volatile("cp.async.cg.shared.global [%0], [%1], 16;" :: "r"(smem), "l"(gmem))
#define CP_COMMIT()  asm volatile("cp.async.commit_group;" ::: "memory")
#define CP_WAIT(n)   asm volatile("cp.async.wait_group %0;" :: "n"(n) : "memory")

__device__ __forceinline__ void ldsm4(uint32_t& r0, uint32_t& r1, uint32_t& r2,
                                      uint32_t& r3, uint32_t addr) {
    asm volatile("ldmatrix.sync.aligned.m8n8.x4.shared.b16 {%0,%1,%2,%3}, [%4];"
                 : "=r"(r0), "=r"(r1), "=r"(r2), "=r"(r3) : "r"(addr));
}
__device__ __forceinline__ void mma16816(float* c, const uint32_t* a,
                                         const uint32_t* b) {
    asm volatile(
        "mma.sync.aligned.m16n8k16.row.col.f32.f16.f16.f32 "
        "{%0,%1,%2,%3}, {%4,%5,%6,%7}, {%8,%9}, {%0,%1,%2,%3};"
        : "+f"(c[0]), "+f"(c[1]), "+f"(c[2]), "+f"(c[3])
        : "r"(a[0]), "r"(a[1]), "r"(a[2]), "r"(a[3]), "r"(b[0]), "r"(b[1]));
}
__device__ __forceinline__ uint32_t pkh2(float a, float b) {
    __half2 t = __floats2half2_rn(a, b);
    return *(uint32_t*)&t;
}

// ---------------- conversion kernels ----------------
__global__ __launch_bounds__(256) void cvt4_kernel(
    const float* __restrict__ in, __half* __restrict__ out, int n4)
{
    int i = blockIdx.x * 256 + threadIdx.x;
    if (i >= n4) return;
    float4 v = ((const float4*)in)[i];
    __half2* o = (__half2*)out;
    o[i * 2]     = __floats2half2_rn(v.x, v.y);
    o[i * 2 + 1] = __floats2half2_rn(v.z, v.w);
}

// Batched: W[k][n] -> Wt[n][k] fp16 for 4 matrices. grid (24,24,4), block (32,8).
__global__ void wcvt4_kernel(const float* __restrict__ W0, const float* __restrict__ W1,
                             const float* __restrict__ W2, const float* __restrict__ W3,
                             __half* __restrict__ out)
{
    __shared__ float t[32][33];
    const int z = blockIdx.z;
    const float* W = (z == 0) ? W0 : (z == 1) ? W1 : (z == 2) ? W2 : W3;
    __half* o = out + (size_t)z * ND * ND;
    const int x0 = blockIdx.x * 32;
    const int y0 = blockIdx.y * 32;
    const int tx = threadIdx.x, ty = threadIdx.y;
#pragma unroll
    for (int r = 0; r < 4; r++)
        t[ty + r * 8][tx] = W[(size_t)(y0 + ty + r * 8) * ND + x0 + tx];
    __syncthreads();
#pragma unroll
    for (int r = 0; r < 4; r++)
        o[(size_t)(x0 + ty + r * 8) * ND + y0 + tx] = __float2half(t[tx][ty + r * 8]);
}

// ---------------- mma.sync GEMM (3-stage, 2 CTA/SM) ----------------
#define BK 64
#define KCH (ND / BK)                    // 12
#define TILE_B  16384                    // 128 rows x 128B
#define STAGE_B (2 * TILE_B)             // 32KB
#define GEMM_SMEM (3 * STAGE_B)          // 96KB

__device__ __forceinline__ uint32_t swz(int row, int colbytes) {
    return (uint32_t)(row * 128 + (colbytes ^ ((row & 7) * 16)));
}

template <int MODE>
__global__ __launch_bounds__(256, 2) void gemm_mma(
    const __half* __restrict__ A, const __half* __restrict__ B,
    float* __restrict__ out, const float* __restrict__ bias,
    __half* __restrict__ q16, __half* __restrict__ k16, __half* __restrict__ vt16)
{
    extern __shared__ char smem[];
    const uint32_t sb = (uint32_t)__cvta_generic_to_shared(smem);
    const int tid  = threadIdx.x;
    const int wid  = tid >> 5;
    const int lane = tid & 31;
    const int bx = blockIdx.x, by = blockIdx.y;
    const int wm = wid >> 2;
    const int wn = wid & 3;

    const size_t aRow = (size_t)by * 128;
    const size_t bRow = (size_t)bx * 128;

    const int ldrow = tid >> 3;
    const int ldck  = tid & 7;

    auto load_chunk = [&](int c, int s) {
        const int kb = c * BK;
        const uint32_t base = sb + s * STAGE_B;
#pragma unroll
        for (int q = 0; q < 4; q++) {
            const int row = ldrow + q * 32;
            const uint32_t so = swz(row, ldck * 16);
            CP_ASYNC16(base + so,          A + (aRow + row) * ND + kb + ldck * 8);
            CP_ASYNC16(base + TILE_B + so, B + (bRow + row) * ND + kb + ldck * 8);
        }
        CP_COMMIT();
    };

    const int a_rofs = ((lane >> 3) & 1) * 8 + (lane & 7);
    const int a_k8   = (lane >> 4) * 8;
    const int b_rofs = (lane >> 4) * 8 + (lane & 7);
    const int b_k8   = ((lane >> 3) & 1) * 8;

    float acc[4][4][4];
#pragma unroll
    for (int mt = 0; mt < 4; mt++)
#pragma unroll
        for (int nt = 0; nt < 4; nt++)
#pragma unroll
            for (int e = 0; e < 4; e++) acc[mt][nt][e] = 0.f;

    load_chunk(0, 0);
    load_chunk(1, 1);

    for (int c = 0; c < KCH; c++) {
        if (c < KCH - 1) { CP_WAIT(1); } else { CP_WAIT(0); }
        __syncthreads();

        const uint32_t base = sb + (c % 3) * STAGE_B;
#pragma unroll
        for (int ks = 0; ks < 4; ks++) {
            uint32_t af[4][4], bf[4][2];
#pragma unroll
            for (int mt = 0; mt < 4; mt++) {
                const int row = wm * 64 + mt * 16 + a_rofs;
                ldsm4(af[mt][0], af[mt][1], af[mt][2], af[mt][3],
                      base + swz(row, (ks * 16 + a_k8) * 2));
            }
#pragma unroll
            for (int p = 0; p < 2; p++) {
                const int row = wn * 32 + p * 16 + b_rofs;
                ldsm4(bf[2 * p][0], bf[2 * p][1], bf[2 * p + 1][0], bf[2 * p + 1][1],
                      base + TILE_B + swz(row, (ks * 16 + b_k8) * 2));
            }
#pragma unroll
            for (int mt = 0; mt < 4; mt++)
#pragma unroll
                for (int nt = 0; nt < 4; nt++)
                    mma16816(acc[mt][nt], af[mt], bf[nt]);
        }
        if (c + 2 < KCH) load_chunk(c + 2, (c + 2) % 3);
    }

    const int g = lane >> 2, t = lane & 3;
#pragma unroll
    for (int mt = 0; mt < 4; mt++) {
#pragma unroll
        for (int nt = 0; nt < 4; nt++) {
            const int col = wn * 32 + nt * 8 + t * 2;
#pragma unroll
            for (int half = 0; half < 2; half++) {
                const int row = wm * 64 + mt * 16 + g + half * 8;
                float2 v = make_float2(acc[mt][nt][half * 2],
                                       acc[mt][nt][half * 2 + 1]);
                if (MODE == 0) {
                    const int tensor = bx / 6;
                    const int wc = (bx % 6) * 128 + col;
                    const int h = wc >> 6, d = wc & 63;
                    if (tensor < 2) {
                        __half* dst = tensor ? k16 : q16;
                        const size_t o = ((size_t)(by * NH + h) * NT + row) * NHD + d;
                        ((__half2*)dst)[o >> 1] = __floats2half2_rn(v.x, v.y);
                    } else {
                        const size_t o = ((size_t)(by * NH + h) * NHD + d) * NT + row;
                        vt16[o]      = __float2half(v.x);
                        vt16[o + NT] = __float2half(v.y);
                    }
                } else {
                    const int gcol = bx * 128 + col;
                    v.x += bias[gcol]; v.y += bias[gcol + 1];
                    *(float2*)(out + (size_t)(by * 128 + row) * ND + gcol) = v;
                }
            }
        }
    }
}

// ---------------- attention: warp-owns-rows, S/P in registers ----------------
// One CTA per (b,h). 8 warps; warp w owns rows 16w..16w+15.
// Smem: K 0 (128x144B=18432), VT 18432 (64x272B=17408), Q 35840 (128x144B).
#define AK_S 0
#define AV_S 18432
#define AQ_S 35840
#define ATTN_SMEM 54272

__global__ __launch_bounds__(256, 2) void attn_tc(
    const __half* __restrict__ q16, const __half* __restrict__ k16,
    const __half* __restrict__ vt16, __half* __restrict__ c16)
{
    extern __shared__ char sm[];
    const uint32_t sb = (uint32_t)__cvta_generic_to_shared(sm);
    const int tid  = threadIdx.x;
    const int w    = tid >> 5;
    const int lane = tid & 31;
    const int bh = blockIdx.x;
    const int b  = bh / NH;
    const int h  = bh - b * NH;

    const size_t base = (size_t)bh * (NT * NHD);

    // ---- cp.async loads ----
    for (int idx = tid; idx < 1024; idx += 256) {        // Q/K: 128 rows x 8 chunks
        const int row = idx >> 3, ck = idx & 7;
        const size_t go = base + row * NHD + ck * 8;
        const uint32_t so = row * 144 + ck * 16;
        CP_ASYNC16(sb + AQ_S + so, q16 + go);
        CP_ASYNC16(sb + AK_S + so, k16 + go);
    }
    for (int idx = tid; idx < 1024; idx += 256) {        // VT: 64 rows x 16 chunks
        const int row = idx >> 4, ck = idx & 15;
        CP_ASYNC16(sb + AV_S + row * 272 + ck * 16, vt16 + base + row * NT + ck * 8);
    }
    CP_COMMIT();
    CP_WAIT(0);
    __syncthreads();

    const int a_rofs = ((lane >> 3) & 1) * 8 + (lane & 7);
    const int a_k8   = (lane >> 4) * 8;
    const int b_rofs = (lane >> 4) * 8 + (lane & 7);
    const int b_k8   = ((lane >> 3) & 1) * 8;
    const int g = lane >> 2, t = lane & 3;

    const int nlim = 2 * w + 2;          // # of n8 tiles with any unmasked col

    // ---- S = Q K^T : rows w*16..w*16+15, cols < 16*(w+1) ----
    float sacc[16][4];
#pragma unroll
    for (int nt = 0; nt < 16; nt++)
#pragma unroll
        for (int e = 0; e < 4; e++) sacc[nt][e] = 0.f;

#pragma unroll
    for (int ks = 0; ks < 4; ks++) {
        uint32_t af[4];
        ldsm4(af[0], af[1], af[2], af[3],
              sb + AQ_S + (w * 16 + a_rofs) * 144 + (ks * 16 + a_k8) * 2);
#pragma unroll
        for (int p = 0; p < 8; p++) {
            if (2 * p < nlim) {
                uint32_t bf[4];
                ldsm4(bf[0], bf[1], bf[2], bf[3],
                      sb + AK_S + (p * 16 + b_rofs) * 144 + (ks * 16 + b_k8) * 2);
                mma16816(sacc[2 * p],     af, bf);
                mma16816(sacc[2 * p + 1], af, bf + 2);
            }
        }
    }

    // ---- register softmax (rows r0 = 16w+g, r1 = r0+8) ----
    const int r0 = w * 16 + g;
    const int r1 = r0 + 8;
    const float scale = 0.125f;
    float m0 = -INFINITY, m1 = -INFINITY;
#pragma unroll
    for (int nt = 0; nt < 16; nt++) {
        if (nt < nlim) {
            const int c0 = nt * 8 + t * 2;
            sacc[nt][0] = (c0 + 0 <= r0) ? sacc[nt][0] : -INFINITY;
            sacc[nt][1] = (c0 + 1 <= r0) ? sacc[nt][1] : -INFINITY;
            sacc[nt][2] = (c0 + 0 <= r1) ? sacc[nt][2] : -INFINITY;
            sacc[nt][3] = (c0 + 1 <= r1) ? sacc[nt][3] : -INFINITY;
            m0 = fmaxf(m0, fmaxf(sacc[nt][0], sacc[nt][1]));
            m1 = fmaxf(m1, fmaxf(sacc[nt][2], sacc[nt][3]));
        }
    }
    m0 = fmaxf(m0, __shfl_xor_sync(0xFFFFFFFFu, m0, 1));
    m0 = fmaxf(m0, __shfl_xor_sync(0xFFFFFFFFu, m0, 2));
    m1 = fmaxf(m1, __shfl_xor_sync(0xFFFFFFFFu, m1, 1));
    m1 = fmaxf(m1, __shfl_xor_sync(0xFFFFFFFFu, m1, 2));

    float s0 = 0.f, s1 = 0.f;
#pragma unroll
    for (int nt = 0; nt < 16; nt++) {
        if (nt < nlim) {
            float e0 = __expf((sacc[nt][0] - m0) * scale);
            float e1 = __expf((sacc[nt][1] - m0) * scale);
            float e2 = __expf((sacc[nt][2] - m1) * scale);
            float e3 = __expf((sacc[nt][3] - m1) * scale);
            sacc[nt][0] = e0; sacc[nt][1] = e1;
            sacc[nt][2] = e2; sacc[nt][3] = e3;
            s0 += e0 + e1;
            s1 += e2 + e3;
        }
    }
    s0 += __shfl_xor_sync(0xFFFFFFFFu, s0, 1);
    s0 += __shfl_xor_sync(0xFFFFFFFFu, s0, 2);
    s1 += __shfl_xor_sync(0xFFFFFFFFu, s1, 1);
    s1 += __shfl_xor_sync(0xFFFFFFFFu, s1, 2);
    const float i0 = 1.f / s0;
    const float i1 = 1.f / s1;

    // ---- P -> fp16 A-fragments (C-frag == A-frag identity) ----
    uint32_t ph[8][4];
#pragma unroll
    for (int q = 0; q < 8; q++) {
        if (q <= w) {
            ph[q][0] = pkh2(sacc[2 * q][0] * i0,     sacc[2 * q][1] * i0);
            ph[q][1] = pkh2(sacc[2 * q][2] * i1,     sacc[2 * q][3] * i1);
            ph[q][2] = pkh2(sacc[2 * q + 1][0] * i0, sacc[2 * q + 1][1] * i0);
            ph[q][3] = pkh2(sacc[2 * q + 1][2] * i1, sacc[2 * q + 1][3] * i1);
        }
    }

    // ---- ctx = P V : M=16 rows, N=64, K only over q <= w ----
    float oacc[8][4];
#pragma unroll
    for (int nt = 0; nt < 8; nt++)
#pragma unroll
        for (int e = 0; e < 4; e++) oacc[nt][e] = 0.f;

#pragma unroll
    for (int q = 0; q < 8; q++) {
        if (q <= w) {
#pragma unroll
            for (int p = 0; p < 4; p++) {
                uint32_t vf[4];
                ldsm4(vf[0], vf[1], vf[2], vf[3],
                      sb + AV_S + (p * 16 + b_rofs) * 272 + (q * 16 + b_k8) * 2);
                mma16816(oacc[2 * p],     ph[q], vf);
                mma16816(oacc[2 * p + 1], ph[q], vf + 2);
            }
        }
    }

    // ---- write ctx fp16 [B,T,D] ----
#pragma unroll
    for (int nt = 0; nt < 8; nt++) {
#pragma unroll
        for (int half = 0; half < 2; half++) {
            const int row = w * 16 + g + half * 8;
            const int col = nt * 8 + t * 2;
            const size_t o = ((size_t)(b * NT + row)) * ND + h * NHD + col;
            ((__half2*)c16)[o >> 1] =
                __floats2half2_rn(oacc[nt][half * 2], oacc[nt][half * 2 + 1]);
        }
    }
}

// ---------------- launch ----------------
extern "C" void kernel_launch(void* const* d_in, const int* in_sizes, int n_in,
                              void* d_out, int out_size)
{
    const float* x  = (const float*)d_in[0];
    const float* Wq = (const float*)d_in[1];
    const float* Wk = (const float*)d_in[2];
    const float* Wv = (const float*)d_in[3];
    const float* Wo = (const float*)d_in[4];
    const float* bo = (const float*)d_in[5];
    float* out = (float*)d_out;

    void *pq, *pk, *pv, *pa, *pw;
    cudaGetSymbolAddress(&pq, g_q16);
    cudaGetSymbolAddress(&pk, g_k16);
    cudaGetSymbolAddress(&pv, g_vt16);
    cudaGetSymbolAddress(&pa, g_a16);
    cudaGetSymbolAddress(&pw, g_wt16);
    __half* a16  = (__half*)pa;
    __half* wt16 = (__half*)pw;

    cudaFuncSetAttribute(gemm_mma<0>,
                         cudaFuncAttributeMaxDynamicSharedMemorySize, GEMM_SMEM);
    cudaFuncSetAttribute(gemm_mma<1>,
                         cudaFuncAttributeMaxDynamicSharedMemorySize, GEMM_SMEM);
    cudaFuncSetAttribute(attn_tc,
                         cudaFuncAttributeMaxDynamicSharedMemorySize, ATTN_SMEM);

    const int n4 = BT * ND / 4;

    // 1) x -> fp16
    cvt4_kernel<<<(n4 + 255) / 256, 256>>>(x, a16, n4);
    // 2) W^T -> fp16, all four in one launch (qkv slots contiguous -> [2304][768])
    {
        dim3 wgrid(ND / 32, ND / 32, 4);
        dim3 wblk(32, 8);
        wcvt4_kernel<<<wgrid, wblk>>>(Wq, Wk, Wv, Wo, wt16);
    }
    // 3) merged QKV projection
    {
        dim3 ggrid(18, BT / 128);
        gemm_mma<0><<<ggrid, 256, GEMM_SMEM>>>(a16, wt16, nullptr, nullptr,
            (__half*)pq, (__half*)pk, (__half*)pv);
    }
    // 4) attention (ctx -> a16)
    attn_tc<<<NB * NH, 256, ATTN_SMEM>>>((const __half*)pq, (const __half*)pk,
                                         (const __half*)pv, a16);
    // 5) output projection with bias
    {
        dim3 ggrid(6, BT / 128);
        gemm_mma<1><<<ggrid, 256, GEMM_SMEM>>>(a16, wt16 + 3 * ND * ND,
            out, bo, nullptr, nullptr, nullptr);
    }
}

// round 15
// speedup vs baseline: 11.1502x; 1.0160x over previous
#include <cuda_runtime.h>
#include <cuda_fp16.h>
#include <cstdint>

// Problem: x[512,128,768] fp32; Wq/k/v/o [768,768]; bo[768]; out[512,128,768] fp32.
#define NB   512
#define NT   128
#define ND   768
#define NH   12
#define NHD  64
#define BT   (NB * NT)          // 65536
#define HSZ  (NB * NH * NT * NHD)
#define NBH  (NB * NH)          // 6144

// ---------------- scratch ----------------
__device__ __align__(256) __half g_q16[HSZ];          // [b,h,t,hd]
__device__ __align__(256) __half g_k16[HSZ];          // [b,h,t,hd]
__device__ __align__(256) __half g_vt16[HSZ];         // [b,h,hd,t]
__device__ __align__(256) __half g_a16[BT * ND];      // x-fp16, then ctx-fp16
__device__ __align__(256) __half g_wt16[4 * ND * ND]; // W^T fp16 (q,k,v,o)

// ---------------- PTX helpers ----------------
#define CP_ASYNC16(smem, gmem) \
    asm volatile("cp.async.cg.shared.global [%0], [%1], 16;" :: "r"(smem), "l"(gmem))
#define CP_COMMIT()  asm volatile("cp.async.commit_group;" ::: "memory")
#define CP_WAIT(n)   asm volatile("cp.async.wait_group %0;" :: "n"(n) : "memory")

__device__ __forceinline__ void ldsm4(uint32_t& r0, uint32_t& r1, uint32_t& r2,
                                      uint32_t& r3, uint32_t addr) {
    asm volatile("ldmatrix.sync.aligned.m8n8.x4.shared.b16 {%0,%1,%2,%3}, [%4];"
                 : "=r"(r0), "=r"(r1), "=r"(r2), "=r"(r3) : "r"(addr));
}
__device__ __forceinline__ void mma16816(float* c, const uint32_t* a,
                                         const uint32_t* b) {
    asm volatile(
        "mma.sync.aligned.m16n8k16.row.col.f32.f16.f16.f32 "
        "{%0,%1,%2,%3}, {%4,%5,%6,%7}, {%8,%9}, {%0,%1,%2,%3};"
        : "+f"(c[0]), "+f"(c[1]), "+f"(c[2]), "+f"(c[3])
        : "r"(a[0]), "r"(a[1]), "r"(a[2]), "r"(a[3]), "r"(b[0]), "r"(b[1]));
}
__device__ __forceinline__ uint32_t pkh2(float a, float b) {
    __half2 t = __floats2half2_rn(a, b);
    return *(uint32_t*)&t;
}

// ---------------- combined conversion kernel ----------------
// blocks [0, NCVT): x fp32 -> fp16.  blocks [NCVT, NCVT+2304): W^T fp16 x4.
#define NCVT (BT * ND / 4 / 256)        // 49152

__global__ __launch_bounds__(256) void conv_all_kernel(
    const float* __restrict__ x, __half* __restrict__ a16,
    const float* __restrict__ W0, const float* __restrict__ W1,
    const float* __restrict__ W2, const float* __restrict__ W3,
    __half* __restrict__ wt16)
{
    const int tid = threadIdx.x;
    if (blockIdx.x < NCVT) {
        const int i = blockIdx.x * 256 + tid;
        float4 v = ((const float4*)x)[i];
        __half2* o = (__half2*)a16;
        o[i * 2]     = __floats2half2_rn(v.x, v.y);
        o[i * 2 + 1] = __floats2half2_rn(v.z, v.w);
    } else {
        __shared__ float t[32][33];
        const int bid = blockIdx.x - NCVT;
        const int z = bid / 576;
        const int rem = bid - z * 576;
        const int bx = rem % 24, by = rem / 24;
        const float* W = (z == 0) ? W0 : (z == 1) ? W1 : (z == 2) ? W2 : W3;
        __half* o = wt16 + (size_t)z * ND * ND;
        const int x0 = bx * 32, y0 = by * 32;
        const int tx = tid & 31, ty = tid >> 5;
#pragma unroll
        for (int r = 0; r < 4; r++)
            t[ty + r * 8][tx] = W[(size_t)(y0 + ty + r * 8) * ND + x0 + tx];
        __syncthreads();
#pragma unroll
        for (int r = 0; r < 4; r++)
            o[(size_t)(x0 + ty + r * 8) * ND + y0 + tx] =
                __float2half(t[tx][ty + r * 8]);
    }
}

// ---------------- mma.sync GEMM (3-stage, 2 CTA/SM) ----------------
#define BK 64
#define KCH (ND / BK)                    // 12
#define TILE_B  16384                    // 128 rows x 128B
#define STAGE_B (2 * TILE_B)             // 32KB
#define GEMM_SMEM (3 * STAGE_B)          // 96KB

__device__ __forceinline__ uint32_t swz(int row, int colbytes) {
    return (uint32_t)(row * 128 + (colbytes ^ ((row & 7) * 16)));
}

template <int MODE>
__global__ __launch_bounds__(256, 2) void gemm_mma(
    const __half* __restrict__ A, const __half* __restrict__ B,
    float* __restrict__ out, const float* __restrict__ bias,
    __half* __restrict__ q16, __half* __restrict__ k16, __half* __restrict__ vt16)
{
    extern __shared__ char smem[];
    const uint32_t sb = (uint32_t)__cvta_generic_to_shared(smem);
    const int tid  = threadIdx.x;
    const int wid  = tid >> 5;
    const int lane = tid & 31;
    const int bx = blockIdx.x, by = blockIdx.y;
    const int wm = wid >> 2;
    const int wn = wid & 3;

    const size_t aRow = (size_t)by * 128;
    const size_t bRow = (size_t)bx * 128;

    const int ldrow = tid >> 3;
    const int ldck  = tid & 7;

    auto load_chunk = [&](int c, int s) {
        const int kb = c * BK;
        const uint32_t base = sb + s * STAGE_B;
#pragma unroll
        for (int q = 0; q < 4; q++) {
            const int row = ldrow + q * 32;
            const uint32_t so = swz(row, ldck * 16);
            CP_ASYNC16(base + so,          A + (aRow + row) * ND + kb + ldck * 8);
            CP_ASYNC16(base + TILE_B + so, B + (bRow + row) * ND + kb + ldck * 8);
        }
        CP_COMMIT();
    };

    const int a_rofs = ((lane >> 3) & 1) * 8 + (lane & 7);
    const int a_k8   = (lane >> 4) * 8;
    const int b_rofs = (lane >> 4) * 8 + (lane & 7);
    const int b_k8   = ((lane >> 3) & 1) * 8;

    float acc[4][4][4];
#pragma unroll
    for (int mt = 0; mt < 4; mt++)
#pragma unroll
        for (int nt = 0; nt < 4; nt++)
#pragma unroll
            for (int e = 0; e < 4; e++) acc[mt][nt][e] = 0.f;

    load_chunk(0, 0);
    load_chunk(1, 1);

    for (int c = 0; c < KCH; c++) {
        if (c < KCH - 1) { CP_WAIT(1); } else { CP_WAIT(0); }
        __syncthreads();

        const uint32_t base = sb + (c % 3) * STAGE_B;
#pragma unroll
        for (int ks = 0; ks < 4; ks++) {
            uint32_t af[4][4], bf[4][2];
#pragma unroll
            for (int mt = 0; mt < 4; mt++) {
                const int row = wm * 64 + mt * 16 + a_rofs;
                ldsm4(af[mt][0], af[mt][1], af[mt][2], af[mt][3],
                      base + swz(row, (ks * 16 + a_k8) * 2));
            }
#pragma unroll
            for (int p = 0; p < 2; p++) {
                const int row = wn * 32 + p * 16 + b_rofs;
                ldsm4(bf[2 * p][0], bf[2 * p][1], bf[2 * p + 1][0], bf[2 * p + 1][1],
                      base + TILE_B + swz(row, (ks * 16 + b_k8) * 2));
            }
#pragma unroll
            for (int mt = 0; mt < 4; mt++)
#pragma unroll
                for (int nt = 0; nt < 4; nt++)
                    mma16816(acc[mt][nt], af[mt], bf[nt]);
        }
        if (c + 2 < KCH) load_chunk(c + 2, (c + 2) % 3);
    }

    const int g = lane >> 2, t = lane & 3;
#pragma unroll
    for (int mt = 0; mt < 4; mt++) {
#pragma unroll
        for (int nt = 0; nt < 4; nt++) {
            const int col = wn * 32 + nt * 8 + t * 2;
#pragma unroll
            for (int half = 0; half < 2; half++) {
                const int row = wm * 64 + mt * 16 + g + half * 8;
                float2 v = make_float2(acc[mt][nt][half * 2],
                                       acc[mt][nt][half * 2 + 1]);
                if (MODE == 0) {
                    const int tensor = bx / 6;
                    const int wc = (bx % 6) * 128 + col;
                    const int h = wc >> 6, d = wc & 63;
                    if (tensor < 2) {
                        __half* dst = tensor ? k16 : q16;
                        const size_t o = ((size_t)(by * NH + h) * NT + row) * NHD + d;
                        ((__half2*)dst)[o >> 1] = __floats2half2_rn(v.x, v.y);
                    } else {
                        const size_t o = ((size_t)(by * NH + h) * NHD + d) * NT + row;
                        vt16[o]      = __float2half(v.x);
                        vt16[o + NT] = __float2half(v.y);
                    }
                } else {
                    const int gcol = bx * 128 + col;
                    v.x += bias[gcol]; v.y += bias[gcol + 1];
                    *(float2*)(out + (size_t)(by * 128 + row) * ND + gcol) = v;
                }
            }
        }
    }
}

// ---------------- attention: persistent CTAs, double-buffered jobs ----------
// 296 CTAs (2/SM); each loops over (b,h) jobs with 2 smem stages of 54272B:
//   per stage: K 0 (128x144B), VT 18432 (64x272B), Q 35840 (128x144B)
// Warp w owns rows 16w..16w+15; S/P live in registers.
#define AK_S 0
#define AV_S 18432
#define AQ_S 35840
#define ATT_STG   54272
#define ATTN_SMEM (2 * ATT_STG)          // 108544
#define ATT_GRID  296

__global__ __launch_bounds__(256, 2) void attn_tc(
    const __half* __restrict__ q16, const __half* __restrict__ k16,
    const __half* __restrict__ vt16, __half* __restrict__ c16)
{
    extern __shared__ char sm[];
    const uint32_t sb = (uint32_t)__cvta_generic_to_shared(sm);
    const int tid  = threadIdx.x;
    const int w    = tid >> 5;
    const int lane = tid & 31;

    const int a_rofs = ((lane >> 3) & 1) * 8 + (lane & 7);
    const int a_k8   = (lane >> 4) * 8;
    const int b_rofs = (lane >> 4) * 8 + (lane & 7);
    const int b_k8   = ((lane >> 3) & 1) * 8;
    const int g = lane >> 2, t = lane & 3;
    const int nlim = 2 * w + 2;

    auto load_job = [&](int bh, int s) {
        const size_t base = (size_t)bh * (NT * NHD);
        const uint32_t stg = sb + s * ATT_STG;
        for (int idx = tid; idx < 1024; idx += 256) {     // Q/K
            const int row = idx >> 3, ck = idx & 7;
            const size_t go = base + row * NHD + ck * 8;
            const uint32_t so = row * 144 + ck * 16;
            CP_ASYNC16(stg + AQ_S + so, q16 + go);
            CP_ASYNC16(stg + AK_S + so, k16 + go);
        }
        for (int idx = tid; idx < 1024; idx += 256) {     // VT
            const int row = idx >> 4, ck = idx & 15;
            CP_ASYNC16(stg + AV_S + row * 272 + ck * 16,
                       vt16 + base + row * NT + ck * 8);
        }
        CP_COMMIT();
    };

    int bh = blockIdx.x;
    if (bh >= NBH) return;
    load_job(bh, 0);

    for (int i = 0; bh < NBH; bh += ATT_GRID, i++) {
        const int s = i & 1;
        const int nbh = bh + ATT_GRID;
        if (nbh < NBH) { load_job(nbh, s ^ 1); CP_WAIT(1); }
        else           { CP_WAIT(0); }
        __syncthreads();

        const uint32_t stg = sb + s * ATT_STG;
        const int b = bh / NH;
        const int h = bh - b * NH;

        // ---- S = Q K^T : rows w*16..w*16+15, cols < 16*(w+1) ----
        float sacc[16][4];
#pragma unroll
        for (int nt = 0; nt < 16; nt++)
#pragma unroll
            for (int e = 0; e < 4; e++) sacc[nt][e] = 0.f;

#pragma unroll
        for (int ks = 0; ks < 4; ks++) {
            uint32_t af[4];
            ldsm4(af[0], af[1], af[2], af[3],
                  stg + AQ_S + (w * 16 + a_rofs) * 144 + (ks * 16 + a_k8) * 2);
#pragma unroll
            for (int p = 0; p < 8; p++) {
                if (2 * p < nlim) {
                    uint32_t bf[4];
                    ldsm4(bf[0], bf[1], bf[2], bf[3],
                          stg + AK_S + (p * 16 + b_rofs) * 144 + (ks * 16 + b_k8) * 2);
                    mma16816(sacc[2 * p],     af, bf);
                    mma16816(sacc[2 * p + 1], af, bf + 2);
                }
            }
        }

        // ---- register softmax ----
        const int r0 = w * 16 + g;
        const int r1 = r0 + 8;
        const float scale = 0.125f;
        float m0 = -INFINITY, m1 = -INFINITY;
#pragma unroll
        for (int nt = 0; nt < 16; nt++) {
            if (nt < nlim) {
                const int c0 = nt * 8 + t * 2;
                sacc[nt][0] = (c0 + 0 <= r0) ? sacc[nt][0] : -INFINITY;
                sacc[nt][1] = (c0 + 1 <= r0) ? sacc[nt][1] : -INFINITY;
                sacc[nt][2] = (c0 + 0 <= r1) ? sacc[nt][2] : -INFINITY;
                sacc[nt][3] = (c0 + 1 <= r1) ? sacc[nt][3] : -INFINITY;
                m0 = fmaxf(m0, fmaxf(sacc[nt][0], sacc[nt][1]));
                m1 = fmaxf(m1, fmaxf(sacc[nt][2], sacc[nt][3]));
            }
        }
        m0 = fmaxf(m0, __shfl_xor_sync(0xFFFFFFFFu, m0, 1));
        m0 = fmaxf(m0, __shfl_xor_sync(0xFFFFFFFFu, m0, 2));
        m1 = fmaxf(m1, __shfl_xor_sync(0xFFFFFFFFu, m1, 1));
        m1 = fmaxf(m1, __shfl_xor_sync(0xFFFFFFFFu, m1, 2));

        float s0 = 0.f, s1 = 0.f;
#pragma unroll
        for (int nt = 0; nt < 16; nt++) {
            if (nt < nlim) {
                float e0 = __expf((sacc[nt][0] - m0) * scale);
                float e1 = __expf((sacc[nt][1] - m0) * scale);
                float e2 = __expf((sacc[nt][2] - m1) * scale);
                float e3 = __expf((sacc[nt][3] - m1) * scale);
                sacc[nt][0] = e0; sacc[nt][1] = e1;
                sacc[nt][2] = e2; sacc[nt][3] = e3;
                s0 += e0 + e1;
                s1 += e2 + e3;
            }
        }
        s0 += __shfl_xor_sync(0xFFFFFFFFu, s0, 1);
        s0 += __shfl_xor_sync(0xFFFFFFFFu, s0, 2);
        s1 += __shfl_xor_sync(0xFFFFFFFFu, s1, 1);
        s1 += __shfl_xor_sync(0xFFFFFFFFu, s1, 2);
        const float i0 = 1.f / s0;
        const float i1 = 1.f / s1;

        // ---- P -> fp16 A-fragments ----
        uint32_t ph[8][4];
#pragma unroll
        for (int q = 0; q < 8; q++) {
            if (q <= w) {
                ph[q][0] = pkh2(sacc[2 * q][0] * i0,     sacc[2 * q][1] * i0);
                ph[q][1] = pkh2(sacc[2 * q][2] * i1,     sacc[2 * q][3] * i1);
                ph[q][2] = pkh2(sacc[2 * q + 1][0] * i0, sacc[2 * q + 1][1] * i0);
                ph[q][3] = pkh2(sacc[2 * q + 1][2] * i1, sacc[2 * q + 1][3] * i1);
            }
        }

        // ---- ctx = P V ----
        float oacc[8][4];
#pragma unroll
        for (int nt = 0; nt < 8; nt++)
#pragma unroll
            for (int e = 0; e < 4; e++) oacc[nt][e] = 0.f;

#pragma unroll
        for (int q = 0; q < 8; q++) {
            if (q <= w) {
#pragma unroll
                for (int p = 0; p < 4; p++) {
                    uint32_t vf[4];
                    ldsm4(vf[0], vf[1], vf[2], vf[3],
                          stg + AV_S + (p * 16 + b_rofs) * 272 + (q * 16 + b_k8) * 2);
                    mma16816(oacc[2 * p],     ph[q], vf);
                    mma16816(oacc[2 * p + 1], ph[q], vf + 2);
                }
            }
        }

        // ---- write ctx fp16 [B,T,D] ----
#pragma unroll
        for (int nt = 0; nt < 8; nt++) {
#pragma unroll
            for (int half = 0; half < 2; half++) {
                const int row = w * 16 + g + half * 8;
                const int col = nt * 8 + t * 2;
                const size_t o = ((size_t)(b * NT + row)) * ND + h * NHD + col;
                ((__half2*)c16)[o >> 1] =
                    __floats2half2_rn(oacc[nt][half * 2], oacc[nt][half * 2 + 1]);
            }
        }
        __syncthreads();   // stage s reusable only after all warps done
    }
}

// ---------------- launch ----------------
extern "C" void kernel_launch(void* const* d_in, const int* in_sizes, int n_in,
                              void* d_out, int out_size)
{
    const float* x  = (const float*)d_in[0];
    const float* Wq = (const float*)d_in[1];
    const float* Wk = (const float*)d_in[2];
    const float* Wv = (const float*)d_in[3];
    const float* Wo = (const float*)d_in[4];
    const float* bo = (const float*)d_in[5];
    float* out = (float*)d_out;

    void *pq, *pk, *pv, *pa, *pw;
    cudaGetSymbolAddress(&pq, g_q16);
    cudaGetSymbolAddress(&pk, g_k16);
    cudaGetSymbolAddress(&pv, g_vt16);
    cudaGetSymbolAddress(&pa, g_a16);
    cudaGetSymbolAddress(&pw, g_wt16);
    __half* a16  = (__half*)pa;
    __half* wt16 = (__half*)pw;

    cudaFuncSetAttribute(gemm_mma<0>,
                         cudaFuncAttributeMaxDynamicSharedMemorySize, GEMM_SMEM);
    cudaFuncSetAttribute(gemm_mma<1>,
                         cudaFuncAttributeMaxDynamicSharedMemorySize, GEMM_SMEM);
    cudaFuncSetAttribute(attn_tc,
                         cudaFuncAttributeMaxDynamicSharedMemorySize, ATTN_SMEM);

    // 1) all conversions in one launch (x -> fp16, 4x W^T -> fp16)
    conv_all_kernel<<<NCVT + 2304, 256>>>(x, a16, Wq, Wk, Wv, Wo, wt16);
    // 2) merged QKV projection
    {
        dim3 ggrid(18, BT / 128);
        gemm_mma<0><<<ggrid, 256, GEMM_SMEM>>>(a16, wt16, nullptr, nullptr,
            (__half*)pq, (__half*)pk, (__half*)pv);
    }
    // 3) persistent double-buffered attention (ctx -> a16)
    attn_tc<<<ATT_GRID, 256, ATTN_SMEM>>>((const __half*)pq, (const __half*)pk,
                                          (const __half*)pv, a16);
    // 4) output projection with bias
    {
        dim3 ggrid(6, BT / 128);
        gemm_mma<1><<<ggrid, 256, GEMM_SMEM>>>(a16, wt16 + 3 * ND * ND,
            out, bo, nullptr, nullptr, nullptr);
    }
}

// round 17
// speedup vs baseline: 11.5604x; 1.0368x over previous
#include <cuda_runtime.h>
#include <cuda_fp16.h>
#include <cstdint>

// Problem: x[512,128,768] fp32; Wq/k/v/o [768,768]; bo[768]; out[512,128,768] fp32.
#define NB   512
#define NT   128
#define ND   768
#define NH   12
#define NHD  64
#define BT   (NB * NT)          // 65536
#define HSZ  (NB * NH * NT * NHD)
#define NBH  (NB * NH)          // 6144

// ---------------- scratch ----------------
__device__ __align__(256) __half g_q16[HSZ];          // [b,h,t,hd]
__device__ __align__(256) __half g_k16[HSZ];          // [b,h,t,hd]
__device__ __align__(256) __half g_vt16[HSZ];         // [b,h,hd,t]
__device__ __align__(256) __half g_a16[BT * ND];      // x-fp16, then ctx-fp16
__device__ __align__(256) __half g_wt16[4 * ND * ND]; // W^T fp16 (q,k,v,o)

// ---------------- PTX helpers ----------------
#define CP_ASYNC16(smem, gmem) \
    asm volatile("cp.async.cg.shared.global [%0], [%1], 16;" :: "r"(smem), "l"(gmem))
#define CP_COMMIT()  asm volatile("cp.async.commit_group;" ::: "memory")
#define CP_WAIT(n)   asm volatile("cp.async.wait_group %0;" :: "n"(n) : "memory")

__device__ __forceinline__ void ldsm4(uint32_t& r0, uint32_t& r1, uint32_t& r2,
                                      uint32_t& r3, uint32_t addr) {
    asm volatile("ldmatrix.sync.aligned.m8n8.x4.shared.b16 {%0,%1,%2,%3}, [%4];"
                 : "=r"(r0), "=r"(r1), "=r"(r2), "=r"(r3) : "r"(addr));
}
__device__ __forceinline__ void mma16816(float* c, const uint32_t* a,
                                         const uint32_t* b) {
    asm volatile(
        "mma.sync.aligned.m16n8k16.row.col.f32.f16.f16.f32 "
        "{%0,%1,%2,%3}, {%4,%5,%6,%7}, {%8,%9}, {%0,%1,%2,%3};"
        : "+f"(c[0]), "+f"(c[1]), "+f"(c[2]), "+f"(c[3])
        : "r"(a[0]), "r"(a[1]), "r"(a[2]), "r"(a[3]), "r"(b[0]), "r"(b[1]));
}
__device__ __forceinline__ uint32_t pkh2(float a, float b) {
    __half2 t = __floats2half2_rn(a, b);
    return *(uint32_t*)&t;
}

// ---------------- combined conversion kernel ----------------
#define NCVT (BT * ND / 4 / 256)        // 49152

__global__ __launch_bounds__(256) void conv_all_kernel(
    const float* __restrict__ x, __half* __restrict__ a16,
    const float* __restrict__ W0, const float* __restrict__ W1,
    const float* __restrict__ W2, const float* __restrict__ W3,
    __half* __restrict__ wt16)
{
    const int tid = threadIdx.x;
    if (blockIdx.x < NCVT) {
        const int i = blockIdx.x * 256 + tid;
        float4 v = ((const float4*)x)[i];
        __half2* o = (__half2*)a16;
        o[i * 2]     = __floats2half2_rn(v.x, v.y);
        o[i * 2 + 1] = __floats2half2_rn(v.z, v.w);
    } else {
        __shared__ float t[32][33];
        const int bid = blockIdx.x - NCVT;
        const int z = bid / 576;
        const int rem = bid - z * 576;
        const int bx = rem % 24, by = rem / 24;
        const float* W = (z == 0) ? W0 : (z == 1) ? W1 : (z == 2) ? W2 : W3;
        __half* o = wt16 + (size_t)z * ND * ND;
        const int x0 = bx * 32, y0 = by * 32;
        const int tx = tid & 31, ty = tid >> 5;
#pragma unroll
        for (int r = 0; r < 4; r++)
            t[ty + r * 8][tx] = W[(size_t)(y0 + ty + r * 8) * ND + x0 + tx];
        __syncthreads();
#pragma unroll
        for (int r = 0; r < 4; r++)
            o[(size_t)(x0 + ty + r * 8) * ND + y0 + tx] =
                __float2half(t[tx][ty + r * 8]);
    }
}

// ---------------- mma.sync GEMM: 128-thr CTA, 2x2 warps, 64x64 warp tile ----
#define BK 64
#define KCH (ND / BK)                    // 12
#define TILE_B  16384                    // 128 rows x 128B
#define STAGE_B (2 * TILE_B)             // 32KB
#define GEMM_SMEM (3 * STAGE_B)          // 96KB

__device__ __forceinline__ uint32_t swz(int row, int colbytes) {
    return (uint32_t)(row * 128 + (colbytes ^ ((row & 7) * 16)));
}

template <int MODE>
__global__ __launch_bounds__(128, 2) void gemm_mma(
    const __half* __restrict__ A, const __half* __restrict__ B,
    float* __restrict__ out, const float* __restrict__ bias,
    __half* __restrict__ q16, __half* __restrict__ k16, __half* __restrict__ vt16)
{
    extern __shared__ char smem[];
    const uint32_t sb = (uint32_t)__cvta_generic_to_shared(smem);
    const int tid  = threadIdx.x;
    const int wid  = tid >> 5;
    const int lane = tid & 31;
    const int bx = blockIdx.x, by = blockIdx.y;
    const int wm = wid >> 1;          // 0..1
    const int wn = wid & 1;           // 0..1

    const size_t aRow = (size_t)by * 128;
    const size_t bRow = (size_t)bx * 128;

    const int ldrow = tid >> 3;       // 0..15, +q*16 covers 0..127
    const int ldck  = tid & 7;

    auto load_chunk = [&](int c, int s) {
        const int kb = c * BK;
        const uint32_t base = sb + s * STAGE_B;
#pragma unroll
        for (int q = 0; q < 8; q++) {
            const int row = ldrow + q * 16;
            const uint32_t so = swz(row, ldck * 16);
            CP_ASYNC16(base + so,          A + (aRow + row) * ND + kb + ldck * 8);
            CP_ASYNC16(base + TILE_B + so, B + (bRow + row) * ND + kb + ldck * 8);
        }
        CP_COMMIT();
    };

    const int a_rofs = ((lane >> 3) & 1) * 8 + (lane & 7);
    const int a_k8   = (lane >> 4) * 8;
    const int b_rofs = (lane >> 4) * 8 + (lane & 7);
    const int b_k8   = ((lane >> 3) & 1) * 8;

    float acc[4][8][4];
#pragma unroll
    for (int mt = 0; mt < 4; mt++)
#pragma unroll
        for (int nt = 0; nt < 8; nt++)
#pragma unroll
            for (int e = 0; e < 4; e++) acc[mt][nt][e] = 0.f;

    load_chunk(0, 0);
    load_chunk(1, 1);

    for (int c = 0; c < KCH; c++) {
        if (c < KCH - 1) { CP_WAIT(1); } else { CP_WAIT(0); }
        __syncthreads();

        const uint32_t base = sb + (c % 3) * STAGE_B;
#pragma unroll
        for (int ks = 0; ks < 4; ks++) {
            uint32_t af[4][4], bf[8][2];
#pragma unroll
            for (int mt = 0; mt < 4; mt++) {
                const int row = wm * 64 + mt * 16 + a_rofs;
                ldsm4(af[mt][0], af[mt][1], af[mt][2], af[mt][3],
                      base + swz(row, (ks * 16 + a_k8) * 2));
            }
#pragma unroll
            for (int p = 0; p < 4; p++) {
                const int row = wn * 64 + p * 16 + b_rofs;
                ldsm4(bf[2 * p][0], bf[2 * p][1], bf[2 * p + 1][0], bf[2 * p + 1][1],
                      base + TILE_B + swz(row, (ks * 16 + b_k8) * 2));
            }
#pragma unroll
            for (int mt = 0; mt < 4; mt++)
#pragma unroll
                for (int nt = 0; nt < 8; nt++)
                    mma16816(acc[mt][nt], af[mt], bf[nt]);
        }
        if (c + 2 < KCH) load_chunk(c + 2, (c + 2) % 3);
    }

    const int g = lane >> 2, t = lane & 3;
#pragma unroll
    for (int mt = 0; mt < 4; mt++) {
#pragma unroll
        for (int nt = 0; nt < 8; nt++) {
            const int col = wn * 64 + nt * 8 + t * 2;
#pragma unroll
            for (int half = 0; half < 2; half++) {
                const int row = wm * 64 + mt * 16 + g + half * 8;
                float2 v = make_float2(acc[mt][nt][half * 2],
                                       acc[mt][nt][half * 2 + 1]);
                if (MODE == 0) {
                    const int tensor = bx / 6;
                    const int wc = (bx % 6) * 128 + col;
                    const int h = wc >> 6, d = wc & 63;
                    if (tensor < 2) {
                        __half* dst = tensor ? k16 : q16;
                        const size_t o = ((size_t)(by * NH + h) * NT + row) * NHD + d;
                        ((__half2*)dst)[o >> 1] = __floats2half2_rn(v.x, v.y);
                    } else {
                        const size_t o = ((size_t)(by * NH + h) * NHD + d) * NT + row;
                        vt16[o]      = __float2half(v.x);
                        vt16[o + NT] = __float2half(v.y);
                    }
                } else {
                    const int gcol = bx * 128 + col;
                    v.x += bias[gcol]; v.y += bias[gcol + 1];
                    *(float2*)(out + (size_t)(by * 128 + row) * ND + gcol) = v;
                }
            }
        }
    }
}

// ---------------- attention: persistent CTAs, double-buffered jobs ----------
#define AK_S 0
#define AV_S 18432
#define AQ_S 35840
#define ATT_STG   54272
#define ATTN_SMEM (2 * ATT_STG)          // 108544
#define ATT_GRID  296

__global__ __launch_bounds__(256, 2) void attn_tc(
    const __half* __restrict__ q16, const __half* __restrict__ k16,
    const __half* __restrict__ vt16, __half* __restrict__ c16)
{
    extern __shared__ char sm[];
    const uint32_t sb = (uint32_t)__cvta_generic_to_shared(sm);
    const int tid  = threadIdx.x;
    const int w    = tid >> 5;
    const int lane = tid & 31;

    const int a_rofs = ((lane >> 3) & 1) * 8 + (lane & 7);
    const int a_k8   = (lane >> 4) * 8;
    const int b_rofs = (lane >> 4) * 8 + (lane & 7);
    const int b_k8   = ((lane >> 3) & 1) * 8;
    const int g = lane >> 2, t = lane & 3;
    const int nlim = 2 * w + 2;

    auto load_job = [&](int bh, int s) {
        const size_t base = (size_t)bh * (NT * NHD);
        const uint32_t stg = sb + s * ATT_STG;
        for (int idx = tid; idx < 1024; idx += 256) {     // Q/K
            const int row = idx >> 3, ck = idx & 7;
            const size_t go = base + row * NHD + ck * 8;
            const uint32_t so = row * 144 + ck * 16;
            CP_ASYNC16(stg + AQ_S + so, q16 + go);
            CP_ASYNC16(stg + AK_S + so, k16 + go);
        }
        for (int idx = tid; idx < 1024; idx += 256) {     // VT
            const int row = idx >> 4, ck = idx & 15;
            CP_ASYNC16(stg + AV_S + row * 272 + ck * 16,
                       vt16 + base + row * NT + ck * 8);
        }
        CP_COMMIT();
    };

    int bh = blockIdx.x;
    if (bh >= NBH) return;
    load_job(bh, 0);

    for (int i = 0; bh < NBH; bh += ATT_GRID, i++) {
        const int s = i & 1;
        const int nbh = bh + ATT_GRID;
        if (nbh < NBH) { load_job(nbh, s ^ 1); CP_WAIT(1); }
        else           { CP_WAIT(0); }
        __syncthreads();

        const uint32_t stg = sb + s * ATT_STG;
        const int b = bh / NH;
        const int h = bh - b * NH;

        float sacc[16][4];
#pragma unroll
        for (int nt = 0; nt < 16; nt++)
#pragma unroll
            for (int e = 0; e < 4; e++) sacc[nt][e] = 0.f;

#pragma unroll
        for (int ks = 0; ks < 4; ks++) {
            uint32_t af[4];
            ldsm4(af[0], af[1], af[2], af[3],
                  stg + AQ_S + (w * 16 + a_rofs) * 144 + (ks * 16 + a_k8) * 2);
#pragma unroll
            for (int p = 0; p < 8; p++) {
                if (2 * p < nlim) {
                    uint32_t bf[4];
                    ldsm4(bf[0], bf[1], bf[2], bf[3],
                          stg + AK_S + (p * 16 + b_rofs) * 144 + (ks * 16 + b_k8) * 2);
                    mma16816(sacc[2 * p],     af, bf);
                    mma16816(sacc[2 * p + 1], af, bf + 2);
                }
            }
        }

        const int r0 = w * 16 + g;
        const int r1 = r0 + 8;
        const float scale = 0.125f;
        float m0 = -INFINITY, m1 = -INFINITY;
#pragma unroll
        for (int nt = 0; nt < 16; nt++) {
            if (nt < nlim) {
                const int c0 = nt * 8 + t * 2;
                sacc[nt][0] = (c0 + 0 <= r0) ? sacc[nt][0] : -INFINITY;
                sacc[nt][1] = (c0 + 1 <= r0) ? sacc[nt][1] : -INFINITY;
                sacc[nt][2] = (c0 + 0 <= r1) ? sacc[nt][2] : -INFINITY;
                sacc[nt][3] = (c0 + 1 <= r1) ? sacc[nt][3] : -INFINITY;
                m0 = fmaxf(m0, fmaxf(sacc[nt][0], sacc[nt][1]));
                m1 = fmaxf(m1, fmaxf(sacc[nt][2], sacc[nt][3]));
            }
        }
        m0 = fmaxf(m0, __shfl_xor_sync(0xFFFFFFFFu, m0, 1));
        m0 = fmaxf(m0, __shfl_xor_sync(0xFFFFFFFFu, m0, 2));
        m1 = fmaxf(m1, __shfl_xor_sync(0xFFFFFFFFu, m1, 1));
        m1 = fmaxf(m1, __shfl_xor_sync(0xFFFFFFFFu, m1, 2));

        float s0 = 0.f, s1 = 0.f;
#pragma unroll
        for (int nt = 0; nt < 16; nt++) {
            if (nt < nlim) {
                float e0 = __expf((sacc[nt][0] - m0) * scale);
                float e1 = __expf((sacc[nt][1] - m0) * scale);
                float e2 = __expf((sacc[nt][2] - m1) * scale);
                float e3 = __expf((sacc[nt][3] - m1) * scale);
                sacc[nt][0] = e0; sacc[nt][1] = e1;
                sacc[nt][2] = e2; sacc[nt][3] = e3;
                s0 += e0 + e1;
                s1 += e2 + e3;
            }
        }
        s0 += __shfl_xor_sync(0xFFFFFFFFu, s0, 1);
        s0 += __shfl_xor_sync(0xFFFFFFFFu, s0, 2);
        s1 += __shfl_xor_sync(0xFFFFFFFFu, s1, 1);
        s1 += __shfl_xor_sync(0xFFFFFFFFu, s1, 2);
        const float i0 = 1.f / s0;
        const float i1 = 1.f / s1;

        uint32_t ph[8][4];
#pragma unroll
        for (int q = 0; q < 8; q++) {
            if (q <= w) {
                ph[q][0] = pkh2(sacc[2 * q][0] * i0,     sacc[2 * q][1] * i0);
                ph[q][1] = pkh2(sacc[2 * q][2] * i1,     sacc[2 * q][3] * i1);
                ph[q][2] = pkh2(sacc[2 * q + 1][0] * i0, sacc[2 * q + 1][1] * i0);
                ph[q][3] = pkh2(sacc[2 * q + 1][2] * i1, sacc[2 * q + 1][3] * i1);
            }
        }

        float oacc[8][4];
#pragma unroll
        for (int nt = 0; nt < 8; nt++)
#pragma unroll
            for (int e = 0; e < 4; e++) oacc[nt][e] = 0.f;

#pragma unroll
        for (int q = 0; q < 8; q++) {
            if (q <= w) {
#pragma unroll
                for (int p = 0; p < 4; p++) {
                    uint32_t vf[4];
                    ldsm4(vf[0], vf[1], vf[2], vf[3],
                          stg + AV_S + (p * 16 + b_rofs) * 272 + (q * 16 + b_k8) * 2);
                    mma16816(oacc[2 * p],     ph[q], vf);
                    mma16816(oacc[2 * p + 1], ph[q], vf + 2);
                }
            }
        }

#pragma unroll
        for (int nt = 0; nt < 8; nt++) {
#pragma unroll
            for (int half = 0; half < 2; half++) {
                const int row = w * 16 + g + half * 8;
                const int col = nt * 8 + t * 2;
                const size_t o = ((size_t)(b * NT + row)) * ND + h * NHD + col;
                ((__half2*)c16)[o >> 1] =
                    __floats2half2_rn(oacc[nt][half * 2], oacc[nt][half * 2 + 1]);
            }
        }
        __syncthreads();
    }
}

// ---------------- launch ----------------
extern "C" void kernel_launch(void* const* d_in, const int* in_sizes, int n_in,
                              void* d_out, int out_size)
{
    const float* x  = (const float*)d_in[0];
    const float* Wq = (const float*)d_in[1];
    const float* Wk = (const float*)d_in[2];
    const float* Wv = (const float*)d_in[3];
    const float* Wo = (const float*)d_in[4];
    const float* bo = (const float*)d_in[5];
    float* out = (float*)d_out;

    void *pq, *pk, *pv, *pa, *pw;
    cudaGetSymbolAddress(&pq, g_q16);
    cudaGetSymbolAddress(&pk, g_k16);
    cudaGetSymbolAddress(&pv, g_vt16);
    cudaGetSymbolAddress(&pa, g_a16);
    cudaGetSymbolAddress(&pw, g_wt16);
    __half* a16  = (__half*)pa;
    __half* wt16 = (__half*)pw;

    cudaFuncSetAttribute(gemm_mma<0>,
                         cudaFuncAttributeMaxDynamicSharedMemorySize, GEMM_SMEM);
    cudaFuncSetAttribute(gemm_mma<1>,
                         cudaFuncAttributeMaxDynamicSharedMemorySize, GEMM_SMEM);
    cudaFuncSetAttribute(attn_tc,
                         cudaFuncAttributeMaxDynamicSharedMemorySize, ATTN_SMEM);

    // 1) all conversions in one launch
    conv_all_kernel<<<NCVT + 2304, 256>>>(x, a16, Wq, Wk, Wv, Wo, wt16);
    // 2) merged QKV projection
    {
        dim3 ggrid(18, BT / 128);
        gemm_mma<0><<<ggrid, 128, GEMM_SMEM>>>(a16, wt16, nullptr, nullptr,
            (__half*)pq, (__half*)pk, (__half*)pv);
    }
    // 3) persistent double-buffered attention (ctx -> a16)
    attn_tc<<<ATT_GRID, 256, ATTN_SMEM>>>((const __half*)pq, (const __half*)pk,
                                          (const __half*)pv, a16);
    // 4) output projection with bias
    {
        dim3 ggrid(6, BT / 128);
        gemm_mma<1><<<ggrid, 128, GEMM_SMEM>>>(a16, wt16 + 3 * ND * ND,
            out, bo, nullptr, nullptr, nullptr);
    }
}